// round 1
// baseline (speedup 1.0000x reference)
#include <cuda_runtime.h>
#include <math.h>

// ---------------- problem constants ----------------
constexpr int kN  = 2048;        // parent voxels
constexpr int kC  = 256;         // in channels
constexpr int kCO = 128;         // out channels
constexpr int kM  = 8 * kN;      // child voxels = 16384
constexpr int kG  = 66;          // padded grid dim (2*32+2)
constexpr int kG3 = kG * kG * kG;

// ---------------- scratch (device globals; no allocs allowed) ----------------
__device__ float g_h   [(kN + 1) * kC];    // silu(LN(feats)), zero pad row at kN
__device__ float g_h1  [(kM + 1) * kCO];   // conv1->LN->silu, zero pad row at kM
__device__ float g_skip[kN * kCO];         // feats @ skip_w + skip_b
__device__ int   g_grid[kG3];              // coord -> child idx (kM = empty)
__device__ int   g_nidx [kM * 27];         // neighbor child idx (kM = empty)
__device__ int   g_nidx1[kM * 27];         // neighbor -> row of g_h (kN = zero)
__device__ int   g_mask[kM];               // subdiv > 0

// ---------------- init: grid sentinel + zero pad rows ----------------
__global__ void init_kernel() {
    int i = blockIdx.x * 256 + threadIdx.x;
    if (i < kG3) g_grid[i] = kM;
    if (i < kC)  g_h [kN * kC  + i] = 0.f;
    if (i < kCO) g_h1[kM * kCO + i] = 0.f;
}

// ---------------- per-parent: subdiv linear + mask + LN + SiLU ----------------
__global__ void row_kernel(const float* __restrict__ feats,
                           const float* __restrict__ n1w,
                           const float* __restrict__ n1b,
                           const float* __restrict__ sdw,   // [C,8]
                           const float* __restrict__ sdb,   // [8]
                           float* __restrict__ subdiv_out)  // [N,8]
{
    const int n = blockIdx.x;
    const int t = threadIdx.x;           // 256 threads
    const int wid = t >> 5, lane = t & 31;
    __shared__ float sf[kC];
    __shared__ float red[8];

    float x = feats[n * kC + t];
    sf[t] = x;
    __syncthreads();

    // subdiv: warp w computes output column w (8 warps, 8 outputs)
    {
        float p = 0.f;
        #pragma unroll
        for (int i = 0; i < 8; ++i) {
            int c = lane + i * 32;
            p += sf[c] * sdw[c * 8 + wid];
        }
        #pragma unroll
        for (int o = 16; o; o >>= 1) p += __shfl_xor_sync(0xffffffffu, p, o);
        if (lane == 0) {
            p += sdb[wid];
            subdiv_out[n * 8 + wid] = p;
            g_mask[n * 8 + wid] = (p > 0.f) ? 1 : 0;
        }
    }

    // LayerNorm (two-pass) + SiLU
    float s = x;
    #pragma unroll
    for (int o = 16; o; o >>= 1) s += __shfl_xor_sync(0xffffffffu, s, o);
    if (lane == 0) red[wid] = s;
    __syncthreads();
    float tot = 0.f;
    #pragma unroll
    for (int i = 0; i < 8; ++i) tot += red[i];
    const float mean = tot * (1.f / kC);
    const float d = x - mean;
    float s2 = d * d;
    #pragma unroll
    for (int o = 16; o; o >>= 1) s2 += __shfl_xor_sync(0xffffffffu, s2, o);
    __syncthreads();                      // everyone done reading red
    if (lane == 0) red[wid] = s2;
    __syncthreads();
    float vtot = 0.f;
    #pragma unroll
    for (int i = 0; i < 8; ++i) vtot += red[i];
    const float var = vtot * (1.f / kC);
    const float y = d * rsqrtf(var + 1e-6f) * n1w[t] + n1b[t];
    g_h[n * kC + t] = y / (1.f + expf(-y));   // silu
}

// ---------------- scatter children into grid ----------------
__global__ void scatter_kernel(const int* __restrict__ coords) {
    int m = blockIdx.x * 256 + threadIdx.x;
    if (m >= kM) return;
    int n = m >> 3, j = m & 7;
    int cx = coords[n * 3 + 0] * 2 + ((j >> 2) & 1);
    int cy = coords[n * 3 + 1] * 2 + ((j >> 1) & 1);
    int cz = coords[n * 3 + 2] * 2 + (j & 1);
    g_grid[((cx + 1) * kG + (cy + 1)) * kG + (cz + 1)] = m;
}

// ---------------- 27-neighbor table ----------------
__global__ void nidx_kernel(const int* __restrict__ coords) {
    int m = blockIdx.x * 256 + threadIdx.x;
    if (m >= kM) return;
    int n = m >> 3, j = m & 7;
    int gx = coords[n * 3 + 0] * 2 + ((j >> 2) & 1) + 1;
    int gy = coords[n * 3 + 1] * 2 + ((j >> 1) & 1) + 1;
    int gz = coords[n * 3 + 2] * 2 + (j & 1) + 1;
    #pragma unroll
    for (int k = 0; k < 27; ++k) {
        int dx = k / 9 - 1, dy = (k / 3) % 3 - 1, dz = k % 3 - 1;
        int nb = g_grid[((gx + dx) * kG + (gy + dy)) * kG + (gz + dz)];
        g_nidx[m * 27 + k] = nb;
        g_nidx1[m * 27 + k] = (nb == kM) ? kN : (g_mask[nb] ? (nb >> 3) : kN);
    }
}

// ---------------- gathered GEMM: MODE 0 skip, 1 conv1, 2 conv2 ----------------
// block tile: 64 rows x 128 cols, TK=32; 256 threads, 4x8 register tile each.
template <int MODE>
__global__ void conv_kernel(const float* __restrict__ ext_src,
                            const float* __restrict__ w,      // [NK,CIN,128]
                            const float* __restrict__ bias,   // [128]
                            float* __restrict__ ext_out)
{
    constexpr int CIN = (MODE == 2) ? 128 : 256;
    constexpr int NK  = (MODE == 0) ? 1 : 27;
    constexpr int TM = 64, TK = 32;

    const float* src = (MODE == 0) ? ext_src : (MODE == 1 ? g_h : g_h1);
    float* out       = (MODE == 0) ? g_skip  : (MODE == 1 ? g_h1 : ext_out);
    const int* nidx  = (MODE == 1) ? g_nidx1 : g_nidx;

    __shared__ float Ws[TK * 128];       // [TK][128]
    __shared__ float Gs[TK][TM + 1];     // padded: conflict-free col writes
    __shared__ int   sIdx[NK * TM];      // [r][k] layout

    const int m0 = blockIdx.x * TM;
    const int t  = threadIdx.x;

    if (MODE == 0) {
        if (t < TM) sIdx[t] = m0 + t;
    } else {
        #pragma unroll
        for (int i = t; i < NK * TM; i += 256)
            sIdx[i] = nidx[m0 * NK + i];            // contiguous
    }
    __syncthreads();

    float acc[4][8];
    #pragma unroll
    for (int i = 0; i < 4; ++i)
        #pragma unroll
        for (int jj = 0; jj < 8; ++jj) acc[i][jj] = 0.f;

    const int tr = (t >> 4) << 2;   // row offset in tile (0..60)
    const int tc = (t & 15) << 3;   // col offset (0..120)

    for (int k = 0; k < NK; ++k) {
        const float* wk = w + (size_t)k * CIN * 128;
        #pragma unroll 1
        for (int c0 = 0; c0 < CIN; c0 += TK) {
            // ---- load W tile (4096 floats as float4) ----
            {
                const float4* wsrc = (const float4*)(wk + c0 * 128);
                float4* wdst = (float4*)Ws;
                #pragma unroll
                for (int i = 0; i < 4; ++i)
                    wdst[t + i * 256] = wsrc[t + i * 256];
            }
            // ---- gather G tile: Gs[c][r] = src[idx[r]][c0+c] ----
            {
                const int c = t & 31;
                #pragma unroll
                for (int i = 0; i < 8; ++i) {
                    int r = (t >> 5) + i * 8;
                    int id = sIdx[r * NK + k];
                    Gs[c][r] = src[(size_t)id * CIN + c0 + c];
                }
            }
            __syncthreads();
            // ---- FMA ----
            #pragma unroll
            for (int kk = 0; kk < TK; ++kk) {
                float a0 = Gs[kk][tr + 0];
                float a1 = Gs[kk][tr + 1];
                float a2 = Gs[kk][tr + 2];
                float a3 = Gs[kk][tr + 3];
                float4 b0 = *(const float4*)&Ws[kk * 128 + tc];
                float4 b1 = *(const float4*)&Ws[kk * 128 + tc + 4];
                float bv[8] = {b0.x, b0.y, b0.z, b0.w, b1.x, b1.y, b1.z, b1.w};
                #pragma unroll
                for (int jj = 0; jj < 8; ++jj) {
                    acc[0][jj] = fmaf(a0, bv[jj], acc[0][jj]);
                    acc[1][jj] = fmaf(a1, bv[jj], acc[1][jj]);
                    acc[2][jj] = fmaf(a2, bv[jj], acc[2][jj]);
                    acc[3][jj] = fmaf(a3, bv[jj], acc[3][jj]);
                }
            }
            __syncthreads();
        }
    }

    // ---- epilogue ----
    #pragma unroll
    for (int i = 0; i < 4; ++i) {
        int m = m0 + tr + i;
        #pragma unroll
        for (int jj = 0; jj < 8; ++jj) {
            int col = tc + jj;
            float v = acc[i][jj] + bias[col];
            if (MODE == 2) {
                v += g_skip[(m >> 3) * kCO + col];
                v = g_mask[m] ? v : 0.f;
            }
            out[(size_t)m * kCO + col] = v;
        }
    }
}

// ---------------- LayerNorm (no affine) + SiLU over g_h1 rows ----------------
__global__ void ln_silu_kernel() {
    const int m = blockIdx.x, t = threadIdx.x;   // 128 threads
    const int wid = t >> 5, lane = t & 31;
    __shared__ float red[4];
    float x = g_h1[m * kCO + t];
    float s = x;
    #pragma unroll
    for (int o = 16; o; o >>= 1) s += __shfl_xor_sync(0xffffffffu, s, o);
    if (lane == 0) red[wid] = s;
    __syncthreads();
    const float mean = (red[0] + red[1] + red[2] + red[3]) * (1.f / kCO);
    const float d = x - mean;
    float s2 = d * d;
    #pragma unroll
    for (int o = 16; o; o >>= 1) s2 += __shfl_xor_sync(0xffffffffu, s2, o);
    __syncthreads();
    if (lane == 0) red[wid] = s2;
    __syncthreads();
    const float var = (red[0] + red[1] + red[2] + red[3]) * (1.f / kCO);
    const float y = d * rsqrtf(var + 1e-6f);
    g_h1[m * kCO + t] = y / (1.f + expf(-y));
}

// ---------------- launch ----------------
extern "C" void kernel_launch(void* const* d_in, const int* in_sizes, int n_in,
                              void* d_out, int out_size)
{
    const float* feats = (const float*)d_in[0];
    const float* n1w   = (const float*)d_in[1];
    const float* n1b   = (const float*)d_in[2];
    const float* sdw   = (const float*)d_in[3];
    const float* sdb   = (const float*)d_in[4];
    const float* c1w   = (const float*)d_in[5];
    const float* c1b   = (const float*)d_in[6];
    const float* c2w   = (const float*)d_in[7];
    const float* c2b   = (const float*)d_in[8];
    const float* skw   = (const float*)d_in[9];
    const float* skb   = (const float*)d_in[10];
    const int*   coords= (const int*)d_in[11];

    float* out        = (float*)d_out;                 // [M, 128]
    float* subdiv_out = out + (size_t)kM * kCO;        // [N, 8]

    init_kernel<<<(kG3 + 255) / 256, 256>>>();
    row_kernel<<<kN, 256>>>(feats, n1w, n1b, sdw, sdb, subdiv_out);
    conv_kernel<0><<<kN / 64, 256>>>(feats, skw, skb, nullptr);   // skip GEMM
    scatter_kernel<<<kM / 256, 256>>>(coords);
    nidx_kernel<<<kM / 256, 256>>>(coords);
    conv_kernel<1><<<kM / 64, 256>>>(nullptr, c1w, c1b, nullptr); // conv1
    ln_silu_kernel<<<kM, 128>>>();
    conv_kernel<2><<<kM / 64, 256>>>(nullptr, c2w, c2b, out);     // conv2 + skip + mask
}

// round 2
// speedup vs baseline: 1.1174x; 1.1174x over previous
#include <cuda_runtime.h>
#include <math.h>

// ---------------- problem constants ----------------
constexpr int kN  = 2048;        // parent voxels
constexpr int kC  = 256;         // in channels
constexpr int kCO = 128;         // out channels
constexpr int kM  = 8 * kN;      // child voxels = 16384
constexpr int kG  = 66;          // padded grid dim (2*32+2)
constexpr int kG3 = kG * kG * kG;

// ---------------- scratch (device globals; no allocs allowed) ----------------
__device__ float g_h   [(kN + 1) * kC];    // silu(LN(feats)), zero pad row at kN
__device__ float g_h1  [(kM + 1) * kCO];   // conv1->LN->silu, zero pad row at kM
__device__ float g_skip[kN * kCO];         // feats @ skip_w + skip_b
__device__ int   g_grid[kG3];              // coord -> child idx (kM = empty)
__device__ int   g_nidx [kM * 27];         // neighbor child idx (kM = empty)
__device__ int   g_nidx1[kM * 27];         // neighbor -> row of g_h (kN = zero)
__device__ int   g_mask[kM];               // subdiv > 0
__device__ int   g_cnt;                    // # active rows
__device__ int   g_list[kM];               // compacted active row ids

// ---------------- packed f32x2 helpers ----------------
__device__ __forceinline__ void fma2(unsigned long long& d,
                                     unsigned long long a,
                                     unsigned long long b) {
    asm("fma.rn.f32x2 %0, %1, %2, %0;" : "+l"(d) : "l"(a), "l"(b));
}
__device__ __forceinline__ unsigned long long bcast2(float a) {
    unsigned long long r;
    unsigned int ai = __float_as_uint(a);
    asm("mov.b64 %0, {%1, %1};" : "=l"(r) : "r"(ai));
    return r;
}
__device__ __forceinline__ float lo32(unsigned long long v) {
    return __uint_as_float((unsigned int)v);
}
__device__ __forceinline__ float hi32(unsigned long long v) {
    return __uint_as_float((unsigned int)(v >> 32));
}

// ---------------- init: grid sentinel + zero pad rows + counter ----------------
__global__ void init_kernel() {
    int i = blockIdx.x * 256 + threadIdx.x;
    if (i < kG3) g_grid[i] = kM;
    if (i < kC)  g_h [kN * kC  + i] = 0.f;
    if (i < kCO) g_h1[kM * kCO + i] = 0.f;
    if (i == 0)  g_cnt = 0;
}

// ---------------- per-parent: subdiv linear + mask + LN + SiLU ----------------
__global__ void row_kernel(const float* __restrict__ feats,
                           const float* __restrict__ n1w,
                           const float* __restrict__ n1b,
                           const float* __restrict__ sdw,   // [C,8]
                           const float* __restrict__ sdb,   // [8]
                           float* __restrict__ subdiv_out)  // [N,8]
{
    const int n = blockIdx.x;
    const int t = threadIdx.x;           // 256 threads
    const int wid = t >> 5, lane = t & 31;
    __shared__ float sf[kC];
    __shared__ float red[8];

    float x = feats[n * kC + t];
    sf[t] = x;
    __syncthreads();

    // subdiv: warp w computes output column w (8 warps, 8 outputs)
    {
        float p = 0.f;
        #pragma unroll
        for (int i = 0; i < 8; ++i) {
            int c = lane + i * 32;
            p += sf[c] * sdw[c * 8 + wid];
        }
        #pragma unroll
        for (int o = 16; o; o >>= 1) p += __shfl_xor_sync(0xffffffffu, p, o);
        if (lane == 0) {
            p += sdb[wid];
            subdiv_out[n * 8 + wid] = p;
            g_mask[n * 8 + wid] = (p > 0.f) ? 1 : 0;
        }
    }

    // LayerNorm (two-pass) + SiLU
    float s = x;
    #pragma unroll
    for (int o = 16; o; o >>= 1) s += __shfl_xor_sync(0xffffffffu, s, o);
    if (lane == 0) red[wid] = s;
    __syncthreads();
    float tot = 0.f;
    #pragma unroll
    for (int i = 0; i < 8; ++i) tot += red[i];
    const float mean = tot * (1.f / kC);
    const float d = x - mean;
    float s2 = d * d;
    #pragma unroll
    for (int o = 16; o; o >>= 1) s2 += __shfl_xor_sync(0xffffffffu, s2, o);
    __syncthreads();
    if (lane == 0) red[wid] = s2;
    __syncthreads();
    float vtot = 0.f;
    #pragma unroll
    for (int i = 0; i < 8; ++i) vtot += red[i];
    const float var = vtot * (1.f / kC);
    const float y = d * rsqrtf(var + 1e-6f) * n1w[t] + n1b[t];
    g_h[n * kC + t] = y / (1.f + expf(-y));   // silu
}

// ---------------- warp-aggregated compaction of active rows ----------------
__global__ void compact_kernel() {
    int m = blockIdx.x * 256 + threadIdx.x;
    int lane = threadIdx.x & 31;
    bool act = (g_mask[m] != 0);
    unsigned ball = __ballot_sync(0xffffffffu, act);
    int cnt = __popc(ball);
    int base = 0;
    if (lane == 0 && cnt) base = atomicAdd(&g_cnt, cnt);
    base = __shfl_sync(0xffffffffu, base, 0);
    if (act) g_list[base + __popc(ball & ((1u << lane) - 1u))] = m;
}

// ---------------- zero output for inactive rows ----------------
__global__ void zero_out_kernel(float4* __restrict__ out) {
    int i = blockIdx.x * 256 + threadIdx.x;   // over kM*32 float4s
    int m = i >> 5;
    if (!g_mask[m]) out[i] = make_float4(0.f, 0.f, 0.f, 0.f);
}

// ---------------- scatter children into grid ----------------
__global__ void scatter_kernel(const int* __restrict__ coords) {
    int m = blockIdx.x * 256 + threadIdx.x;
    if (m >= kM) return;
    int n = m >> 3, j = m & 7;
    int cx = coords[n * 3 + 0] * 2 + ((j >> 2) & 1);
    int cy = coords[n * 3 + 1] * 2 + ((j >> 1) & 1);
    int cz = coords[n * 3 + 2] * 2 + (j & 1);
    g_grid[((cx + 1) * kG + (cy + 1)) * kG + (cz + 1)] = m;
}

// ---------------- 27-neighbor table ----------------
__global__ void nidx_kernel(const int* __restrict__ coords) {
    int m = blockIdx.x * 256 + threadIdx.x;
    if (m >= kM) return;
    int n = m >> 3, j = m & 7;
    int gx = coords[n * 3 + 0] * 2 + ((j >> 2) & 1) + 1;
    int gy = coords[n * 3 + 1] * 2 + ((j >> 1) & 1) + 1;
    int gz = coords[n * 3 + 2] * 2 + (j & 1) + 1;
    #pragma unroll
    for (int k = 0; k < 27; ++k) {
        int dx = k / 9 - 1, dy = (k / 3) % 3 - 1, dz = k % 3 - 1;
        int nb = g_grid[((gx + dx) * kG + (gy + dy)) * kG + (gz + dz)];
        g_nidx[m * 27 + k] = nb;
        g_nidx1[m * 27 + k] = (nb == kM) ? kN : (g_mask[nb] ? (nb >> 3) : kN);
    }
}

// ---------------- gathered GEMM: MODE 0 skip, 1 conv1, 2 conv2(compacted) ----
// block tile: 64 rows x 128 cols, TK=32; 256 threads, 4x8 register tile each,
// inner product via packed fma.rn.f32x2 (FFMA2).
template <int MODE>
__global__ void __launch_bounds__(256, 2)
conv_kernel(const float* __restrict__ ext_src,
            const float* __restrict__ w,      // [NK,CIN,128]
            const float* __restrict__ bias,   // [128]
            float* __restrict__ ext_out)
{
    constexpr int CIN = (MODE == 2) ? 128 : 256;
    constexpr int NK  = (MODE == 0) ? 1 : 27;
    constexpr int TM = 64, TK = 32;

    const float* src = (MODE == 0) ? ext_src : (MODE == 1 ? g_h : g_h1);
    float* out       = (MODE == 0) ? g_skip  : (MODE == 1 ? g_h1 : ext_out);

    __shared__ float Ws[TK * 128];       // [TK][128]
    __shared__ float Gs[TK][TM + 1];     // padded: conflict-free scattered writes
    __shared__ int   sIdx[NK * TM];      // [r][k]
    __shared__ int   sRows[TM];          // MODE 2: compacted global row ids

    const int m0 = blockIdx.x * TM;
    const int t  = threadIdx.x;
    int cnt = 0;

    if (MODE == 0) {
        if (t < TM) sIdx[t] = m0 + t;
    } else if (MODE == 1) {
        #pragma unroll
        for (int i = t; i < NK * TM; i += 256)
            sIdx[i] = g_nidx1[m0 * NK + i];            // contiguous
    } else {
        cnt = g_cnt;
        if (m0 >= cnt) return;                          // whole tile inactive
        if (t < TM) {
            int s = m0 + t;
            sRows[t] = g_list[s < cnt ? s : cnt - 1];   // pad with last active
        }
        __syncthreads();
        for (int i = t; i < NK * TM; i += 256) {
            int r = i / NK, k = i - r * NK;
            sIdx[i] = g_nidx[sRows[r] * NK + k];
        }
    }
    __syncthreads();

    unsigned long long acc2[4][4];
    #pragma unroll
    for (int i = 0; i < 4; ++i)
        #pragma unroll
        for (int j = 0; j < 4; ++j) acc2[i][j] = 0ull;

    const int tr = (t >> 4) << 2;   // row offset in tile (0..60)
    const int tc = (t & 15) << 3;   // col offset (0..120)

    for (int k = 0; k < NK; ++k) {
        const float* wk = w + (size_t)k * CIN * 128;
        #pragma unroll 1
        for (int c0 = 0; c0 < CIN; c0 += TK) {
            // ---- load W tile (4096 floats as float4) ----
            {
                const float4* wsrc = (const float4*)(wk + c0 * 128);
                float4* wdst = (float4*)Ws;
                #pragma unroll
                for (int i = 0; i < 4; ++i)
                    wdst[t + i * 256] = wsrc[t + i * 256];
            }
            // ---- gather G tile: Gs[c][r] = src[idx[r]][c0+c] ----
            {
                const int c = t & 31;
                #pragma unroll
                for (int i = 0; i < 8; ++i) {
                    int r = (t >> 5) + i * 8;
                    int id = sIdx[r * NK + k];
                    Gs[c][r] = src[(size_t)id * CIN + c0 + c];
                }
            }
            __syncthreads();
            // ---- packed FFMA2 ----
            #pragma unroll
            for (int kk = 0; kk < TK; ++kk) {
                unsigned long long aa0 = bcast2(Gs[kk][tr + 0]);
                unsigned long long aa1 = bcast2(Gs[kk][tr + 1]);
                unsigned long long aa2 = bcast2(Gs[kk][tr + 2]);
                unsigned long long aa3 = bcast2(Gs[kk][tr + 3]);
                ulonglong2 q0 = *(const ulonglong2*)&Ws[kk * 128 + tc];
                ulonglong2 q1 = *(const ulonglong2*)&Ws[kk * 128 + tc + 4];
                unsigned long long bb0 = q0.x, bb1 = q0.y, bb2 = q1.x, bb3 = q1.y;
                fma2(acc2[0][0], aa0, bb0); fma2(acc2[0][1], aa0, bb1);
                fma2(acc2[0][2], aa0, bb2); fma2(acc2[0][3], aa0, bb3);
                fma2(acc2[1][0], aa1, bb0); fma2(acc2[1][1], aa1, bb1);
                fma2(acc2[1][2], aa1, bb2); fma2(acc2[1][3], aa1, bb3);
                fma2(acc2[2][0], aa2, bb0); fma2(acc2[2][1], aa2, bb1);
                fma2(acc2[2][2], aa2, bb2); fma2(acc2[2][3], aa2, bb3);
                fma2(acc2[3][0], aa3, bb0); fma2(acc2[3][1], aa3, bb1);
                fma2(acc2[3][2], aa3, bb2); fma2(acc2[3][3], aa3, bb3);
            }
            __syncthreads();
        }
    }

    // ---- epilogue ----
    #pragma unroll
    for (int i = 0; i < 4; ++i) {
        if (MODE == 2) {
            int slot = m0 + tr + i;
            if (slot >= cnt) continue;
            int m = sRows[tr + i];
            const float* sk = &g_skip[(size_t)(m >> 3) * kCO];
            #pragma unroll
            for (int j = 0; j < 4; ++j) {
                int col = tc + 2 * j;
                out[(size_t)m * kCO + col]     = lo32(acc2[i][j]) + bias[col]     + sk[col];
                out[(size_t)m * kCO + col + 1] = hi32(acc2[i][j]) + bias[col + 1] + sk[col + 1];
            }
        } else {
            int m = m0 + tr + i;
            #pragma unroll
            for (int j = 0; j < 4; ++j) {
                int col = tc + 2 * j;
                out[(size_t)m * kCO + col]     = lo32(acc2[i][j]) + bias[col];
                out[(size_t)m * kCO + col + 1] = hi32(acc2[i][j]) + bias[col + 1];
            }
        }
    }
}

// ---------------- LayerNorm (no affine) + SiLU over g_h1 rows ----------------
__global__ void ln_silu_kernel() {
    const int m = blockIdx.x, t = threadIdx.x;   // 128 threads
    const int wid = t >> 5, lane = t & 31;
    __shared__ float red[4];
    float x = g_h1[m * kCO + t];
    float s = x;
    #pragma unroll
    for (int o = 16; o; o >>= 1) s += __shfl_xor_sync(0xffffffffu, s, o);
    if (lane == 0) red[wid] = s;
    __syncthreads();
    const float mean = (red[0] + red[1] + red[2] + red[3]) * (1.f / kCO);
    const float d = x - mean;
    float s2 = d * d;
    #pragma unroll
    for (int o = 16; o; o >>= 1) s2 += __shfl_xor_sync(0xffffffffu, s2, o);
    __syncthreads();
    if (lane == 0) red[wid] = s2;
    __syncthreads();
    const float var = (red[0] + red[1] + red[2] + red[3]) * (1.f / kCO);
    const float y = d * rsqrtf(var + 1e-6f);
    g_h1[m * kCO + t] = y / (1.f + expf(-y));
}

// ---------------- launch ----------------
extern "C" void kernel_launch(void* const* d_in, const int* in_sizes, int n_in,
                              void* d_out, int out_size)
{
    const float* feats = (const float*)d_in[0];
    const float* n1w   = (const float*)d_in[1];
    const float* n1b   = (const float*)d_in[2];
    const float* sdw   = (const float*)d_in[3];
    const float* sdb   = (const float*)d_in[4];
    const float* c1w   = (const float*)d_in[5];
    const float* c1b   = (const float*)d_in[6];
    const float* c2w   = (const float*)d_in[7];
    const float* c2b   = (const float*)d_in[8];
    const float* skw   = (const float*)d_in[9];
    const float* skb   = (const float*)d_in[10];
    const int*   coords= (const int*)d_in[11];

    float* out        = (float*)d_out;                 // [M, 128]
    float* subdiv_out = out + (size_t)kM * kCO;        // [N, 8]

    init_kernel<<<(kG3 + 255) / 256, 256>>>();
    row_kernel<<<kN, 256>>>(feats, n1w, n1b, sdw, sdb, subdiv_out);
    compact_kernel<<<kM / 256, 256>>>();
    zero_out_kernel<<<kM * 32 / 256, 256>>>((float4*)out);
    conv_kernel<0><<<kN / 64, 256>>>(feats, skw, skb, nullptr);   // skip GEMM
    scatter_kernel<<<kM / 256, 256>>>(coords);
    nidx_kernel<<<kM / 256, 256>>>(coords);
    conv_kernel<1><<<kM / 64, 256>>>(nullptr, c1w, c1b, nullptr); // conv1
    ln_silu_kernel<<<kM, 128>>>();
    conv_kernel<2><<<kM / 64, 256>>>(nullptr, c2w, c2b, out);     // conv2 (compacted)
}

// round 3
// speedup vs baseline: 3.4888x; 3.1221x over previous
#include <cuda_runtime.h>
#include <math.h>

// ---------------- problem constants ----------------
constexpr int kN  = 2048;        // parent voxels
constexpr int kC  = 256;         // in channels
constexpr int kCO = 128;         // out channels
constexpr int kM  = 8 * kN;      // child voxels = 16384
constexpr int kG  = 66;          // padded grid dim (2*32+2)
constexpr int kG3 = kG * kG * kG;

// ---------------- scratch (device globals; no allocs allowed) ----------------
__device__ float g_h    [(kN + 1) * kC];    // silu(LN(feats)), zero pad row kN
__device__ float g_h1   [(kM + 1) * kCO];   // conv1->LN->silu, zero pad row kM
__device__ float g_h1acc[(kM + 1) * kCO];   // conv1 accumulator (pre-bias)
__device__ float g_skip [kN * kCO];         // feats @ skip_w + skip_b
__device__ float g_dump [kCO];              // scatter target for pad pairs
__device__ int   g_grid[kG3];               // coord -> child idx (kM = empty)
__device__ int   g_nidx [kM * 27];          // neighbor child idx (kM = empty)
__device__ int   g_nidx1[kM * 27];          // neighbor -> parent row (kN = zero)
__device__ int   g_mask[kM];                // subdiv > 0
__device__ int   g_cnt;                     // # active rows
__device__ int   g_list[kM];                // compacted active row ids
// tap-major pair lists (per-tap contiguous segments, 64-padded)
__device__ int   g_in1 [kM * 27], g_out1[kM * 27];
__device__ int   g_in2 [kM * 27], g_out2[kM * 27];
__device__ int   g_cnt1[27], g_start1[27], g_plen1[27];
__device__ int   g_cnt2[27], g_start2[27], g_plen2[27];

// ---------------- init: zero accumulators/out, grid sentinel, pads -----------
__global__ void init_kernel(float* __restrict__ out) {
    int i = blockIdx.x * 256 + threadIdx.x;       // covers (kM+1)*kCO
    if (i < (kM + 1) * kCO) g_h1acc[i] = 0.f;
    if (i < kM * kCO)       out[i] = 0.f;
    if (i < kG3)            g_grid[i] = kM;
    if (i < kC)             g_h [kN * kC  + i] = 0.f;
    if (i < kCO)            g_h1[kM * kCO + i] = 0.f;
    if (i == 0)             g_cnt = 0;
}

// ---------------- per-parent: subdiv linear + mask + LN + SiLU ----------------
__global__ void row_kernel(const float* __restrict__ feats,
                           const float* __restrict__ n1w,
                           const float* __restrict__ n1b,
                           const float* __restrict__ sdw,   // [C,8]
                           const float* __restrict__ sdb,   // [8]
                           float* __restrict__ subdiv_out)  // [N,8]
{
    const int n = blockIdx.x;
    const int t = threadIdx.x;           // 256 threads
    const int wid = t >> 5, lane = t & 31;
    __shared__ float sf[kC];
    __shared__ float red[8];

    float x = feats[n * kC + t];
    sf[t] = x;
    __syncthreads();

    // subdiv: warp w computes output column w
    {
        float p = 0.f;
        #pragma unroll
        for (int i = 0; i < 8; ++i) {
            int c = lane + i * 32;
            p += sf[c] * sdw[c * 8 + wid];
        }
        #pragma unroll
        for (int o = 16; o; o >>= 1) p += __shfl_xor_sync(0xffffffffu, p, o);
        if (lane == 0) {
            p += sdb[wid];
            subdiv_out[n * 8 + wid] = p;
            g_mask[n * 8 + wid] = (p > 0.f) ? 1 : 0;
        }
    }

    // LayerNorm (two-pass) + SiLU
    float s = x;
    #pragma unroll
    for (int o = 16; o; o >>= 1) s += __shfl_xor_sync(0xffffffffu, s, o);
    if (lane == 0) red[wid] = s;
    __syncthreads();
    float tot = 0.f;
    #pragma unroll
    for (int i = 0; i < 8; ++i) tot += red[i];
    const float mean = tot * (1.f / kC);
    const float d = x - mean;
    float s2 = d * d;
    #pragma unroll
    for (int o = 16; o; o >>= 1) s2 += __shfl_xor_sync(0xffffffffu, s2, o);
    __syncthreads();
    if (lane == 0) red[wid] = s2;
    __syncthreads();
    float vtot = 0.f;
    #pragma unroll
    for (int i = 0; i < 8; ++i) vtot += red[i];
    const float var = vtot * (1.f / kC);
    const float y = d * rsqrtf(var + 1e-6f) * n1w[t] + n1b[t];
    g_h[n * kC + t] = y / (1.f + expf(-y));   // silu
}

// ---------------- warp-aggregated compaction of active rows ----------------
__global__ void compact_kernel() {
    int m = blockIdx.x * 256 + threadIdx.x;
    int lane = threadIdx.x & 31;
    bool act = (g_mask[m] != 0);
    unsigned ball = __ballot_sync(0xffffffffu, act);
    int cnt = __popc(ball);
    int base = 0;
    if (lane == 0 && cnt) base = atomicAdd(&g_cnt, cnt);
    base = __shfl_sync(0xffffffffu, base, 0);
    if (act) g_list[base + __popc(ball & ((1u << lane) - 1u))] = m;
}

// ---------------- scatter children into grid ----------------
__global__ void scatter_kernel(const int* __restrict__ coords) {
    int m = blockIdx.x * 256 + threadIdx.x;
    if (m >= kM) return;
    int n = m >> 3, j = m & 7;
    int cx = coords[n * 3 + 0] * 2 + ((j >> 2) & 1);
    int cy = coords[n * 3 + 1] * 2 + ((j >> 1) & 1);
    int cz = coords[n * 3 + 2] * 2 + (j & 1);
    g_grid[((cx + 1) * kG + (cy + 1)) * kG + (cz + 1)] = m;
}

// ---------------- 27-neighbor table ----------------
__global__ void nidx_kernel(const int* __restrict__ coords) {
    int m = blockIdx.x * 256 + threadIdx.x;
    if (m >= kM) return;
    int n = m >> 3, j = m & 7;
    int gx = coords[n * 3 + 0] * 2 + ((j >> 2) & 1) + 1;
    int gy = coords[n * 3 + 1] * 2 + ((j >> 1) & 1) + 1;
    int gz = coords[n * 3 + 2] * 2 + (j & 1) + 1;
    #pragma unroll
    for (int k = 0; k < 27; ++k) {
        int dx = k / 9 - 1, dy = (k / 3) % 3 - 1, dz = k % 3 - 1;
        int nb = g_grid[((gx + dx) * kG + (gy + dy)) * kG + (gz + dz)];
        g_nidx[m * 27 + k] = nb;
        g_nidx1[m * 27 + k] = (nb == kM) ? kN : (g_mask[nb] ? (nb >> 3) : kN);
    }
}

// ---------------- pair-list building (tap-major, deterministic) -------------
// MODE 1: conv1 pairs (in = parent row of masked neighbor), MODE 2: conv2.
template <int MODE>
__device__ __forceinline__ bool tap_flag(int m, int k, int& in_id) {
    if (MODE == 1) {
        in_id = g_nidx1[m * 27 + k];
        return in_id != kN;
    } else {
        in_id = g_nidx[m * 27 + k];
        return g_mask[m] && (in_id != kM);
    }
}

template <int MODE>
__global__ void tap_count_kernel() {
    const int k = blockIdx.x, t = threadIdx.x;   // 27 blocks x 256 thr
    int cnt = 0;
    #pragma unroll 4
    for (int r = 0; r < 64; ++r) {
        int in_id;
        if (tap_flag<MODE>(t * 64 + r, k, in_id)) ++cnt;
    }
    __shared__ int sh[256];
    sh[t] = cnt;
    __syncthreads();
    for (int o = 128; o; o >>= 1) {
        if (t < o) sh[t] += sh[t + o];
        __syncthreads();
    }
    if (t == 0) (MODE == 1 ? g_cnt1 : g_cnt2)[k] = sh[0];
}

__global__ void tap_scan_kernel() {
    if (threadIdx.x != 0) return;
    int s1 = 0, s2 = 0;
    for (int k = 0; k < 27; ++k) {
        int c = g_cnt1[k], p = (c + 63) & ~63;
        g_start1[k] = s1; g_plen1[k] = p; s1 += p;
        c = g_cnt2[k]; p = (c + 63) & ~63;
        g_start2[k] = s2; g_plen2[k] = p; s2 += p;
    }
}

template <int MODE>
__global__ void tap_fill_kernel() {
    const int k = blockIdx.x, t = threadIdx.x;
    int* __restrict__ pin  = (MODE == 1) ? g_in1  : g_in2;
    int* __restrict__ pout = (MODE == 1) ? g_out1 : g_out2;
    const int start = (MODE == 1 ? g_start1 : g_start2)[k];

    int cnt = 0;
    #pragma unroll 4
    for (int r = 0; r < 64; ++r) {
        int in_id;
        if (tap_flag<MODE>(t * 64 + r, k, in_id)) ++cnt;
    }
    __shared__ int ex[257];
    ex[t + 1] = cnt;
    __syncthreads();
    if (t == 0) {
        ex[0] = 0;
        for (int i = 0; i < 256; ++i) ex[i + 1] += ex[i];
    }
    __syncthreads();
    int w = start + ex[t];
    for (int r = 0; r < 64; ++r) {
        int m = t * 64 + r, in_id;
        if (tap_flag<MODE>(m, k, in_id)) {
            pin[w] = in_id;
            pout[w] = m;
            ++w;
        }
    }
    if (t == 0) {   // pad to 64-multiple: zero input row, dump output
        int tot = ex[256];
        int plen = (MODE == 1 ? g_plen1 : g_plen2)[k];
        for (int i = tot; i < plen; ++i) {
            pin[start + i] = (MODE == 1) ? kN : kM;   // zero rows
            pout[start + i] = -1;                      // dump
        }
    }
}

// ---------------- tap-segment GEMM: 64 pairs x 128 cols, atomic scatter -----
template <int MODE>
__global__ void __launch_bounds__(256)
tapgemm_kernel(const float* __restrict__ w,      // [27,CIN,128]
               float* __restrict__ ext_out)
{
    constexpr int CIN = (MODE == 1) ? kC : kCO;
    constexpr int TM = 64, TK = 32;

    const int k = blockIdx.x >> 8;
    const int s = blockIdx.x & 255;
    const int plen = (MODE == 1 ? g_plen1 : g_plen2)[k];
    if (s * TM >= plen) return;
    const int base = (MODE == 1 ? g_start1 : g_start2)[k] + s * TM;

    const float* __restrict__ src = (MODE == 1) ? g_h : g_h1;
    float* __restrict__ dstbase   = (MODE == 1) ? g_h1acc : ext_out;
    const int* __restrict__ pin   = (MODE == 1) ? g_in1  : g_in2;
    const int* __restrict__ pout  = (MODE == 1) ? g_out1 : g_out2;

    __shared__ float Ws[TK * 128];
    __shared__ float Gs[TK][TM + 1];
    __shared__ int   sIdx[TM];
    __shared__ int   sOut[TM];

    const int t = threadIdx.x;
    if (t < TM) {
        sIdx[t] = pin[base + t];
        sOut[t] = pout[base + t];
    }
    __syncthreads();

    float acc[4][8];
    #pragma unroll
    for (int i = 0; i < 4; ++i)
        #pragma unroll
        for (int j = 0; j < 8; ++j) acc[i][j] = 0.f;

    const int tr = (t >> 4) << 2;   // 0..60
    const int tc = (t & 15) << 3;   // 0..120
    const float* wk = w + (size_t)k * CIN * 128;

    #pragma unroll 1
    for (int c0 = 0; c0 < CIN; c0 += TK) {
        {   // W tile: 4096 floats
            const float4* wsrc = (const float4*)(wk + c0 * 128);
            float4* wdst = (float4*)Ws;
            #pragma unroll
            for (int i = 0; i < 4; ++i)
                wdst[t + i * 256] = wsrc[t + i * 256];
        }
        {   // gather tile
            const int c = t & 31;
            #pragma unroll
            for (int i = 0; i < 8; ++i) {
                int r = (t >> 5) + i * 8;
                Gs[c][r] = src[(size_t)sIdx[r] * CIN + c0 + c];
            }
        }
        __syncthreads();
        #pragma unroll
        for (int kk = 0; kk < TK; ++kk) {
            float a0 = Gs[kk][tr + 0];
            float a1 = Gs[kk][tr + 1];
            float a2 = Gs[kk][tr + 2];
            float a3 = Gs[kk][tr + 3];
            float4 b0 = *(const float4*)&Ws[kk * 128 + tc];
            float4 b1 = *(const float4*)&Ws[kk * 128 + tc + 4];
            float bv[8] = {b0.x, b0.y, b0.z, b0.w, b1.x, b1.y, b1.z, b1.w};
            #pragma unroll
            for (int j = 0; j < 8; ++j) {
                acc[0][j] = fmaf(a0, bv[j], acc[0][j]);
                acc[1][j] = fmaf(a1, bv[j], acc[1][j]);
                acc[2][j] = fmaf(a2, bv[j], acc[2][j]);
                acc[3][j] = fmaf(a3, bv[j], acc[3][j]);
            }
        }
        __syncthreads();
    }

    // ---- atomic scatter epilogue ----
    #pragma unroll
    for (int i = 0; i < 4; ++i) {
        int o = sOut[tr + i];
        float* dst = (o < 0) ? g_dump : dstbase + (size_t)o * kCO;
        #pragma unroll
        for (int j = 0; j < 8; ++j)
            atomicAdd(&dst[tc + j], acc[i][j]);
    }
}

// ---------------- skip GEMM (dense, 2048 rows) ----------------
__global__ void __launch_bounds__(256)
skip_kernel(const float* __restrict__ feats,
            const float* __restrict__ w,      // [256,128]
            const float* __restrict__ bias)
{
    constexpr int TM = 64, TK = 32, CIN = kC;
    __shared__ float Ws[TK * 128];
    __shared__ float Gs[TK][TM + 1];
    const int m0 = blockIdx.x * TM;
    const int t = threadIdx.x;

    float acc[4][8];
    #pragma unroll
    for (int i = 0; i < 4; ++i)
        #pragma unroll
        for (int j = 0; j < 8; ++j) acc[i][j] = 0.f;

    const int tr = (t >> 4) << 2;
    const int tc = (t & 15) << 3;

    #pragma unroll 1
    for (int c0 = 0; c0 < CIN; c0 += TK) {
        {
            const float4* wsrc = (const float4*)(w + c0 * 128);
            float4* wdst = (float4*)Ws;
            #pragma unroll
            for (int i = 0; i < 4; ++i)
                wdst[t + i * 256] = wsrc[t + i * 256];
        }
        {
            const int c = t & 31;
            #pragma unroll
            for (int i = 0; i < 8; ++i) {
                int r = (t >> 5) + i * 8;
                Gs[c][r] = feats[(size_t)(m0 + r) * CIN + c0 + c];
            }
        }
        __syncthreads();
        #pragma unroll
        for (int kk = 0; kk < TK; ++kk) {
            float a0 = Gs[kk][tr + 0];
            float a1 = Gs[kk][tr + 1];
            float a2 = Gs[kk][tr + 2];
            float a3 = Gs[kk][tr + 3];
            float4 b0 = *(const float4*)&Ws[kk * 128 + tc];
            float4 b1 = *(const float4*)&Ws[kk * 128 + tc + 4];
            float bv[8] = {b0.x, b0.y, b0.z, b0.w, b1.x, b1.y, b1.z, b1.w};
            #pragma unroll
            for (int j = 0; j < 8; ++j) {
                acc[0][j] = fmaf(a0, bv[j], acc[0][j]);
                acc[1][j] = fmaf(a1, bv[j], acc[1][j]);
                acc[2][j] = fmaf(a2, bv[j], acc[2][j]);
                acc[3][j] = fmaf(a3, bv[j], acc[3][j]);
            }
        }
        __syncthreads();
    }
    #pragma unroll
    for (int i = 0; i < 4; ++i) {
        int m = m0 + tr + i;
        #pragma unroll
        for (int j = 0; j < 8; ++j)
            g_skip[(size_t)m * kCO + tc + j] = acc[i][j] + bias[tc + j];
    }
}

// ---------------- h1 epilogue: +bias -> LN(no affine) -> SiLU ----------------
__global__ void h1_ep_kernel(const float* __restrict__ c1b) {
    const int m = blockIdx.x, t = threadIdx.x;   // 128 threads
    const int wid = t >> 5, lane = t & 31;
    __shared__ float red[4];
    float x = g_h1acc[m * kCO + t] + c1b[t];
    float s = x;
    #pragma unroll
    for (int o = 16; o; o >>= 1) s += __shfl_xor_sync(0xffffffffu, s, o);
    if (lane == 0) red[wid] = s;
    __syncthreads();
    const float mean = (red[0] + red[1] + red[2] + red[3]) * (1.f / kCO);
    const float d = x - mean;
    float s2 = d * d;
    #pragma unroll
    for (int o = 16; o; o >>= 1) s2 += __shfl_xor_sync(0xffffffffu, s2, o);
    __syncthreads();
    if (lane == 0) red[wid] = s2;
    __syncthreads();
    const float var = (red[0] + red[1] + red[2] + red[3]) * (1.f / kCO);
    const float y = d * rsqrtf(var + 1e-6f);
    g_h1[m * kCO + t] = y / (1.f + expf(-y));
}

// ---------------- out epilogue: += bias + skip (active rows only) ------------
__global__ void out_ep_kernel(float* __restrict__ out,
                              const float* __restrict__ c2b) {
    if ((int)blockIdx.x >= g_cnt) return;
    const int m = g_list[blockIdx.x], t = threadIdx.x;   // 128 threads
    out[(size_t)m * kCO + t] += c2b[t] + g_skip[(size_t)(m >> 3) * kCO + t];
}

// ---------------- launch ----------------
extern "C" void kernel_launch(void* const* d_in, const int* in_sizes, int n_in,
                              void* d_out, int out_size)
{
    const float* feats = (const float*)d_in[0];
    const float* n1w   = (const float*)d_in[1];
    const float* n1b   = (const float*)d_in[2];
    const float* sdw   = (const float*)d_in[3];
    const float* sdb   = (const float*)d_in[4];
    const float* c1w   = (const float*)d_in[5];
    const float* c1b   = (const float*)d_in[6];
    const float* c2w   = (const float*)d_in[7];
    const float* c2b   = (const float*)d_in[8];
    const float* skw   = (const float*)d_in[9];
    const float* skb   = (const float*)d_in[10];
    const int*   coords= (const int*)d_in[11];

    float* out        = (float*)d_out;                 // [M, 128]
    float* subdiv_out = out + (size_t)kM * kCO;        // [N, 8]

    const int initN = ((kM + 1) * kCO + 255) / 256;

    init_kernel<<<initN, 256>>>(out);
    row_kernel<<<kN, 256>>>(feats, n1w, n1b, sdw, sdb, subdiv_out);
    compact_kernel<<<kM / 256, 256>>>();
    skip_kernel<<<kN / 64, 256>>>(feats, skw, skb);
    scatter_kernel<<<kM / 256, 256>>>(coords);
    nidx_kernel<<<kM / 256, 256>>>(coords);
    // pair lists
    tap_count_kernel<1><<<27, 256>>>();
    tap_count_kernel<2><<<27, 256>>>();
    tap_scan_kernel<<<1, 32>>>();
    tap_fill_kernel<1><<<27, 256>>>();
    tap_fill_kernel<2><<<27, 256>>>();
    // conv1 (sparse taps) -> h1 epilogue -> conv2 (sparse taps) -> out epilogue
    tapgemm_kernel<1><<<27 * 256, 256>>>(c1w, nullptr);
    h1_ep_kernel<<<kM, 128>>>(c1b);
    tapgemm_kernel<2><<<27 * 256, 256>>>(c2w, out);
    out_ep_kernel<<<kM, 128>>>(out, c2b);
}

// round 7
// speedup vs baseline: 5.8115x; 1.6658x over previous
#include <cuda_runtime.h>
#include <cuda_bf16.h>
#include <math.h>

// ---------------- problem constants ----------------
constexpr int kN  = 2048;
constexpr int kC  = 256;
constexpr int kCO = 128;
constexpr int kM  = 8 * kN;      // 16384
constexpr int kG  = 66;
constexpr int kG3 = kG * kG * kG;

// ---------------- scratch globals (NEVER passed as kernel args from host) ----
__device__ __nv_bfloat16 g_hhi [(kN + 1) * kC];
__device__ __nv_bfloat16 g_hlo [(kN + 1) * kC];
__device__ __nv_bfloat16 g_h1hi[(kM + 1) * kCO];
__device__ __nv_bfloat16 g_h1lo[(kM + 1) * kCO];
__device__ float g_h1acc[kM * kCO];
__device__ float g_skip [kN * kCO];
__device__ int   g_grid[kG3];
__device__ int   g_nidx [kM * 27];
__device__ int   g_nidx1[kM * 27];
__device__ int   g_mask[kM];
__device__ int   g_cnt;
__device__ int   g_list[kM];
__device__ int   g_in1 [kM * 27 + 27 * 128], g_out1[kM * 27 + 27 * 128];
__device__ int   g_in2 [kM * 27 + 27 * 128], g_out2[kM * 27 + 27 * 128];
__device__ int   g_cnt1[27], g_start1[27], g_plen1[27];
__device__ int   g_cnt2[27], g_start2[27], g_plen2[27];
// transposed bf16 weights: [27][128(n)][CIN(c)]
__device__ __nv_bfloat16 g_w1hi[27 * 128 * kC],  g_w1lo[27 * 128 * kC];
__device__ __nv_bfloat16 g_w2hi[27 * 128 * kCO], g_w2lo[27 * 128 * kCO];

// ---------------- ptx helpers ----------------
__device__ __forceinline__ unsigned smem_u32(const void* p) {
    unsigned a;
    asm("{ .reg .u64 t; cvta.to.shared.u64 t, %1; cvt.u32.u64 %0, t; }"
        : "=r"(a) : "l"(p));
    return a;
}
__device__ __forceinline__ unsigned lds_u32(unsigned addr) {
    unsigned v;
    asm volatile("ld.shared.b32 %0, [%1];" : "=r"(v) : "r"(addr));
    return v;
}
__device__ __forceinline__ void mma16816(float* d, const unsigned* a,
                                         const unsigned* b) {
    asm volatile(
        "mma.sync.aligned.m16n8k16.row.col.f32.bf16.bf16.f32 "
        "{%0,%1,%2,%3}, {%4,%5,%6,%7}, {%8,%9}, {%0,%1,%2,%3};"
        : "+f"(d[0]), "+f"(d[1]), "+f"(d[2]), "+f"(d[3])
        : "r"(a[0]), "r"(a[1]), "r"(a[2]), "r"(a[3]), "r"(b[0]), "r"(b[1]));
}

// ---------------- init ----------------
__global__ void init_kernel(float* __restrict__ out) {
    int i = blockIdx.x * 256 + threadIdx.x;
    if (i < kM * kCO) { g_h1acc[i] = 0.f; out[i] = 0.f; }
    if (i < kG3) g_grid[i] = kM;
    if (i < kC)  { g_hhi[kN * kC + i] = __float2bfloat16(0.f);
                   g_hlo[kN * kC + i] = __float2bfloat16(0.f); }
    if (i < kCO) { g_h1hi[kM * kCO + i] = __float2bfloat16(0.f);
                   g_h1lo[kM * kCO + i] = __float2bfloat16(0.f); }
    if (i == 0)  g_cnt = 0;
}

// ---------------- weight transpose + bf16 split (targets via MODE) ----------
template <int MODE>
__global__ void cvtw_kernel(const float* __restrict__ w) {
    constexpr int CIN = (MODE == 1) ? kC : kCO;
    __nv_bfloat16* __restrict__ hi = (MODE == 1) ? g_w1hi : g_w2hi;
    __nv_bfloat16* __restrict__ lo = (MODE == 1) ? g_w1lo : g_w2lo;
    int idx = blockIdx.x * 256 + threadIdx.x;      // 27*128*CIN
    if (idx >= 27 * 128 * CIN) return;
    int c = idx % CIN;
    int n = (idx / CIN) & 127;
    int k = idx / (CIN * 128);
    float v = w[(size_t)k * CIN * 128 + (size_t)c * 128 + n];
    __nv_bfloat16 h = __float2bfloat16(v);
    hi[idx] = h;
    lo[idx] = __float2bfloat16(v - __bfloat162float(h));
}

// ---------------- per-parent: subdiv + mask + LN + SiLU (-> bf16 hi/lo) -----
__global__ void row_kernel(const float* __restrict__ feats,
                           const float* __restrict__ n1w,
                           const float* __restrict__ n1b,
                           const float* __restrict__ sdw,
                           const float* __restrict__ sdb,
                           float* __restrict__ subdiv_out) {
    const int n = blockIdx.x;
    const int t = threadIdx.x;           // 256
    const int wid = t >> 5, lane = t & 31;
    __shared__ float sf[kC];
    __shared__ float red[8];

    float x = feats[n * kC + t];
    sf[t] = x;
    __syncthreads();

    {
        float p = 0.f;
        #pragma unroll
        for (int i = 0; i < 8; ++i) {
            int c = lane + i * 32;
            p += sf[c] * sdw[c * 8 + wid];
        }
        #pragma unroll
        for (int o = 16; o; o >>= 1) p += __shfl_xor_sync(0xffffffffu, p, o);
        if (lane == 0) {
            p += sdb[wid];
            subdiv_out[n * 8 + wid] = p;
            g_mask[n * 8 + wid] = (p > 0.f) ? 1 : 0;
        }
    }

    float s = x;
    #pragma unroll
    for (int o = 16; o; o >>= 1) s += __shfl_xor_sync(0xffffffffu, s, o);
    if (lane == 0) red[wid] = s;
    __syncthreads();
    float tot = 0.f;
    #pragma unroll
    for (int i = 0; i < 8; ++i) tot += red[i];
    const float mean = tot * (1.f / kC);
    const float d = x - mean;
    float s2 = d * d;
    #pragma unroll
    for (int o = 16; o; o >>= 1) s2 += __shfl_xor_sync(0xffffffffu, s2, o);
    __syncthreads();
    if (lane == 0) red[wid] = s2;
    __syncthreads();
    float vtot = 0.f;
    #pragma unroll
    for (int i = 0; i < 8; ++i) vtot += red[i];
    const float var = vtot * (1.f / kC);
    const float y = d * rsqrtf(var + 1e-6f) * n1w[t] + n1b[t];
    const float h = y / (1.f + expf(-y));
    __nv_bfloat16 hh = __float2bfloat16(h);
    g_hhi[n * kC + t] = hh;
    g_hlo[n * kC + t] = __float2bfloat16(h - __bfloat162float(hh));
}

// ---------------- compaction ----------------
__global__ void compact_kernel() {
    int m = blockIdx.x * 256 + threadIdx.x;
    int lane = threadIdx.x & 31;
    bool act = (g_mask[m] != 0);
    unsigned ball = __ballot_sync(0xffffffffu, act);
    int cnt = __popc(ball);
    int base = 0;
    if (lane == 0 && cnt) base = atomicAdd(&g_cnt, cnt);
    base = __shfl_sync(0xffffffffu, base, 0);
    if (act) g_list[base + __popc(ball & ((1u << lane) - 1u))] = m;
}

// ---------------- grid scatter + neighbor table ----------------
__global__ void scatter_kernel(const int* __restrict__ coords) {
    int m = blockIdx.x * 256 + threadIdx.x;
    if (m >= kM) return;
    int n = m >> 3, j = m & 7;
    int cx = coords[n * 3 + 0] * 2 + ((j >> 2) & 1);
    int cy = coords[n * 3 + 1] * 2 + ((j >> 1) & 1);
    int cz = coords[n * 3 + 2] * 2 + (j & 1);
    g_grid[((cx + 1) * kG + (cy + 1)) * kG + (cz + 1)] = m;
}

__global__ void nidx_kernel(const int* __restrict__ coords) {
    int m = blockIdx.x * 256 + threadIdx.x;
    if (m >= kM) return;
    int n = m >> 3, j = m & 7;
    int gx = coords[n * 3 + 0] * 2 + ((j >> 2) & 1) + 1;
    int gy = coords[n * 3 + 1] * 2 + ((j >> 1) & 1) + 1;
    int gz = coords[n * 3 + 2] * 2 + (j & 1) + 1;
    #pragma unroll
    for (int k = 0; k < 27; ++k) {
        int dx = k / 9 - 1, dy = (k / 3) % 3 - 1, dz = k % 3 - 1;
        int nb = g_grid[((gx + dx) * kG + (gy + dy)) * kG + (gz + dz)];
        g_nidx[m * 27 + k] = nb;
        g_nidx1[m * 27 + k] = (nb == kM) ? kN : (g_mask[nb] ? (nb >> 3) : kN);
    }
}

// ---------------- pair-list building (pad to 128) ----------------
template <int MODE>
__device__ __forceinline__ bool tap_flag(int m, int k, int& in_id) {
    if (MODE == 1) {
        in_id = g_nidx1[m * 27 + k];
        return in_id != kN;
    } else {
        in_id = g_nidx[m * 27 + k];
        return g_mask[m] && (in_id != kM);
    }
}

template <int MODE>
__global__ void tap_count_kernel() {
    const int k = blockIdx.x, t = threadIdx.x;
    int cnt = 0;
    #pragma unroll 4
    for (int r = 0; r < 64; ++r) {
        int in_id;
        if (tap_flag<MODE>(t * 64 + r, k, in_id)) ++cnt;
    }
    __shared__ int sh[256];
    sh[t] = cnt;
    __syncthreads();
    for (int o = 128; o; o >>= 1) {
        if (t < o) sh[t] += sh[t + o];
        __syncthreads();
    }
    if (t == 0) (MODE == 1 ? g_cnt1 : g_cnt2)[k] = sh[0];
}

__global__ void tap_scan_kernel() {
    if (threadIdx.x != 0) return;
    int s1 = 0, s2 = 0;
    for (int k = 0; k < 27; ++k) {
        int c = g_cnt1[k], p = (c + 127) & ~127;
        g_start1[k] = s1; g_plen1[k] = p; s1 += p;
        c = g_cnt2[k]; p = (c + 127) & ~127;
        g_start2[k] = s2; g_plen2[k] = p; s2 += p;
    }
}

template <int MODE>
__global__ void tap_fill_kernel() {
    const int k = blockIdx.x, t = threadIdx.x;
    int* __restrict__ pin  = (MODE == 1) ? g_in1  : g_in2;
    int* __restrict__ pout = (MODE == 1) ? g_out1 : g_out2;
    const int start = (MODE == 1 ? g_start1 : g_start2)[k];

    int cnt = 0;
    #pragma unroll 4
    for (int r = 0; r < 64; ++r) {
        int in_id;
        if (tap_flag<MODE>(t * 64 + r, k, in_id)) ++cnt;
    }
    __shared__ int ex[257];
    ex[t + 1] = cnt;
    __syncthreads();
    if (t == 0) {
        ex[0] = 0;
        for (int i = 0; i < 256; ++i) ex[i + 1] += ex[i];
    }
    __syncthreads();
    int w = start + ex[t];
    for (int r = 0; r < 64; ++r) {
        int m = t * 64 + r, in_id;
        if (tap_flag<MODE>(m, k, in_id)) {
            pin[w] = in_id;
            pout[w] = m;
            ++w;
        }
    }
    if (t == 0) {
        int tot = ex[256];
        int plen = (MODE == 1 ? g_plen1 : g_plen2)[k];
        for (int i = tot; i < plen; ++i) {
            pin[start + i] = (MODE == 1) ? kN : kM;   // zero bf16 rows
            pout[start + i] = -1;
        }
    }
}

// ---------------- tensor-core tap GEMM via mma.sync (HMMA) -------------------
// Block tile M=128 x N=128, BK=32, 256 threads (8 warps as 4x2, warp 32x64).
// Fragments via plain ld.shared.b32 per the PTX m16n8k16 fragment spec.
// Static smem (~42KB). bf16 3-split, atomic scatter. All globals via MODE.
// ext_out: harness pointer used only for MODE 2.
template <int MODE>
__global__ void __launch_bounds__(256)
tapgemm_mma(float* __restrict__ ext_out)
{
    constexpr int CIN = (MODE == 1) ? kC : kCO;
    constexpr int BK  = 32;
    constexpr int NCH = CIN / BK;
    constexpr int LDB = 80;                 // tile row stride in bytes (40 bf16)

    __shared__ __align__(16) __nv_bfloat16 Ahi[128 * 40], Alo[128 * 40];
    __shared__ __align__(16) __nv_bfloat16 Bhi[128 * 40], Blo[128 * 40];
    __shared__ int sIdx[128], sOut[128];

    const int k = blockIdx.x >> 7;
    const int s = blockIdx.x & 127;
    const int plen = (MODE == 1 ? g_plen1 : g_plen2)[k];
    if (s * 128 >= plen) return;
    const int base = (MODE == 1 ? g_start1 : g_start2)[k] + s * 128;

    const __nv_bfloat16* __restrict__ shi = (MODE == 1) ? g_hhi : g_h1hi;
    const __nv_bfloat16* __restrict__ slo = (MODE == 1) ? g_hlo : g_h1lo;
    const __nv_bfloat16* __restrict__ whi = (MODE == 1) ? g_w1hi : g_w2hi;
    const __nv_bfloat16* __restrict__ wlo = (MODE == 1) ? g_w1lo : g_w2lo;
    const int* __restrict__ pin  = (MODE == 1) ? g_in1  : g_in2;
    const int* __restrict__ pout = (MODE == 1) ? g_out1 : g_out2;
    float* __restrict__ dstbase  = (MODE == 1) ? g_h1acc : ext_out;

    const int t = threadIdx.x;
    if (t < 128) {
        sIdx[t] = pin[base + t];
        sOut[t] = pout[base + t];
    }
    __syncthreads();

    const unsigned uAhi = smem_u32(Ahi), uAlo = smem_u32(Alo);
    const unsigned uBhi = smem_u32(Bhi), uBlo = smem_u32(Blo);

    const int warp = t >> 5, lane = t & 31;
    const int g = lane >> 2, tid = lane & 3;
    const int wm = (warp & 3) * 32;    // m offset
    const int wn = (warp >> 2) * 64;   // n offset

    float acc[2][8][4];
    #pragma unroll
    for (int i = 0; i < 2; ++i)
        #pragma unroll
        for (int j = 0; j < 8; ++j)
            #pragma unroll
            for (int q = 0; q < 4; ++q) acc[i][j][q] = 0.f;

    const size_t wko = (size_t)k * 128 * CIN;

    for (int ch = 0; ch < NCH; ++ch) {
        const int c0 = ch * BK;
        // ---- load tiles: 512 uint4 per tile (4 x 16B chunks per 128 rows) ----
        #pragma unroll
        for (int i = 0; i < 2; ++i) {
            int q = t + i * 256;            // 0..511
            int r = q >> 2, j = q & 3;      // row, 16B chunk
            const size_t arow = (size_t)sIdx[r] * CIN + c0;
            const size_t brow = wko + (size_t)r * CIN + c0;
            int toff = r * LDB + j * 16;
            *(uint4*)((char*)Ahi + toff) = *((const uint4*)(shi + arow) + j);
            *(uint4*)((char*)Alo + toff) = *((const uint4*)(slo + arow) + j);
            *(uint4*)((char*)Bhi + toff) = *((const uint4*)(whi + brow) + j);
            *(uint4*)((char*)Blo + toff) = *((const uint4*)(wlo + brow) + j);
        }
        __syncthreads();

        #pragma unroll
        for (int ks = 0; ks < BK / 16; ++ks) {
            const int kb0 = (ks * 16 + 2 * tid) * 2;       // k byte offset, lo 8
            const int kb1 = kb0 + 16;                      // k byte offset, hi 8
            // A frags per spec: a0=(g,klo) a1=(g+8,klo) a2=(g,khi) a3=(g+8,khi)
            unsigned ah[2][4], al[2][4];
            #pragma unroll
            for (int mt = 0; mt < 2; ++mt) {
                int r0 = (wm + mt * 16 + g) * LDB;
                int r1 = r0 + 8 * LDB;
                ah[mt][0] = lds_u32(uAhi + r0 + kb0);
                ah[mt][1] = lds_u32(uAhi + r1 + kb0);
                ah[mt][2] = lds_u32(uAhi + r0 + kb1);
                ah[mt][3] = lds_u32(uAhi + r1 + kb1);
                al[mt][0] = lds_u32(uAlo + r0 + kb0);
                al[mt][1] = lds_u32(uAlo + r1 + kb0);
                al[mt][2] = lds_u32(uAlo + r0 + kb1);
                al[mt][3] = lds_u32(uAlo + r1 + kb1);
            }
            // B frags per spec: b0=(klo, n=g), b1=(khi, n=g); 8 n-slices
            #pragma unroll
            for (int na = 0; na < 8; ++na) {
                int nr = (wn + na * 8 + g) * LDB;
                unsigned bh[2], bl[2];
                bh[0] = lds_u32(uBhi + nr + kb0);
                bh[1] = lds_u32(uBhi + nr + kb1);
                bl[0] = lds_u32(uBlo + nr + kb0);
                bl[1] = lds_u32(uBlo + nr + kb1);
                #pragma unroll
                for (int mt = 0; mt < 2; ++mt) {
                    mma16816(acc[mt][na], ah[mt], bh);
                    mma16816(acc[mt][na], ah[mt], bl);
                    mma16816(acc[mt][na], al[mt], bh);
                }
            }
        }
        __syncthreads();
    }

    // ---- atomic scatter epilogue (D frag: c0=(g,2tid) c1=(g,2tid+1)
    //      c2=(g+8,2tid) c3=(g+8,2tid+1)) ----
    const int cq = tid * 2;
    #pragma unroll
    for (int mt = 0; mt < 2; ++mt) {
        #pragma unroll
        for (int half = 0; half < 2; ++half) {
            int m = wm + mt * 16 + g + half * 8;
            int orow = sOut[m];
            if (orow < 0) continue;
            float* dst = dstbase + (size_t)orow * kCO + wn;
            #pragma unroll
            for (int na = 0; na < 8; ++na) {
                atomicAdd(&dst[na * 8 + cq],     acc[mt][na][half * 2]);
                atomicAdd(&dst[na * 8 + cq + 1], acc[mt][na][half * 2 + 1]);
            }
        }
    }
}

// ---------------- skip GEMM (fp32 SIMT, TM=32 -> 64 blocks) ----------------
__global__ void __launch_bounds__(256)
skip_kernel(const float* __restrict__ feats,
            const float* __restrict__ w,
            const float* __restrict__ bias)
{
    constexpr int TM = 32, TK = 32, CIN = kC;
    __shared__ float Ws[TK * 128];
    __shared__ float Gs[TK][TM + 1];
    const int m0 = blockIdx.x * TM;
    const int t = threadIdx.x;

    float acc[2][8];
    #pragma unroll
    for (int i = 0; i < 2; ++i)
        #pragma unroll
        for (int j = 0; j < 8; ++j) acc[i][j] = 0.f;

    const int tr = (t >> 4) << 1;
    const int tc = (t & 15) << 3;

    #pragma unroll 1
    for (int c0 = 0; c0 < CIN; c0 += TK) {
        {
            const float4* wsrc = (const float4*)(w + c0 * 128);
            float4* wdst = (float4*)Ws;
            #pragma unroll
            for (int i = 0; i < 4; ++i)
                wdst[t + i * 256] = wsrc[t + i * 256];
        }
        {
            const int c = t & 31;
            #pragma unroll
            for (int i = 0; i < 4; ++i) {
                int r = (t >> 5) + i * 8;
                Gs[c][r] = feats[(size_t)(m0 + r) * CIN + c0 + c];
            }
        }
        __syncthreads();
        #pragma unroll
        for (int kk = 0; kk < TK; ++kk) {
            float a0 = Gs[kk][tr + 0];
            float a1 = Gs[kk][tr + 1];
            float4 b0 = *(const float4*)&Ws[kk * 128 + tc];
            float4 b1 = *(const float4*)&Ws[kk * 128 + tc + 4];
            float bv[8] = {b0.x, b0.y, b0.z, b0.w, b1.x, b1.y, b1.z, b1.w};
            #pragma unroll
            for (int j = 0; j < 8; ++j) {
                acc[0][j] = fmaf(a0, bv[j], acc[0][j]);
                acc[1][j] = fmaf(a1, bv[j], acc[1][j]);
            }
        }
        __syncthreads();
    }
    #pragma unroll
    for (int i = 0; i < 2; ++i) {
        int m = m0 + tr + i;
        #pragma unroll
        for (int j = 0; j < 8; ++j)
            g_skip[(size_t)m * kCO + tc + j] = acc[i][j] + bias[tc + j];
    }
}

// ---------------- h1 epilogue: +bias -> LN -> SiLU -> bf16 hi/lo -------------
__global__ void h1_ep_kernel(const float* __restrict__ c1b) {
    const int m = blockIdx.x, t = threadIdx.x;   // 128
    const int wid = t >> 5, lane = t & 31;
    __shared__ float red[4];
    float x = g_h1acc[m * kCO + t] + c1b[t];
    float s = x;
    #pragma unroll
    for (int o = 16; o; o >>= 1) s += __shfl_xor_sync(0xffffffffu, s, o);
    if (lane == 0) red[wid] = s;
    __syncthreads();
    const float mean = (red[0] + red[1] + red[2] + red[3]) * (1.f / kCO);
    const float d = x - mean;
    float s2 = d * d;
    #pragma unroll
    for (int o = 16; o; o >>= 1) s2 += __shfl_xor_sync(0xffffffffu, s2, o);
    __syncthreads();
    if (lane == 0) red[wid] = s2;
    __syncthreads();
    const float var = (red[0] + red[1] + red[2] + red[3]) * (1.f / kCO);
    const float y = d * rsqrtf(var + 1e-6f);
    const float h = y / (1.f + expf(-y));
    __nv_bfloat16 hh = __float2bfloat16(h);
    g_h1hi[m * kCO + t] = hh;
    g_h1lo[m * kCO + t] = __float2bfloat16(h - __bfloat162float(hh));
}

// ---------------- out epilogue: += bias + skip (active rows) -----------------
__global__ void out_ep_kernel(float* __restrict__ out,
                              const float* __restrict__ c2b) {
    if ((int)blockIdx.x >= g_cnt) return;
    const int m = g_list[blockIdx.x], t = threadIdx.x;   // 128
    out[(size_t)m * kCO + t] += c2b[t] + g_skip[(size_t)(m >> 3) * kCO + t];
}

// ---------------- launch (ONLY harness pointers cross the boundary) ----------
extern "C" void kernel_launch(void* const* d_in, const int* in_sizes, int n_in,
                              void* d_out, int out_size)
{
    const float* feats = (const float*)d_in[0];
    const float* n1w   = (const float*)d_in[1];
    const float* n1b   = (const float*)d_in[2];
    const float* sdw   = (const float*)d_in[3];
    const float* sdb   = (const float*)d_in[4];
    const float* c1w   = (const float*)d_in[5];
    const float* c1b   = (const float*)d_in[6];
    const float* c2w   = (const float*)d_in[7];
    const float* c2b   = (const float*)d_in[8];
    const float* skw   = (const float*)d_in[9];
    const float* skb   = (const float*)d_in[10];
    const int*   coords= (const int*)d_in[11];

    float* out        = (float*)d_out;
    float* subdiv_out = out + (size_t)kM * kCO;

    init_kernel<<<(kM * kCO + 255) / 256, 256>>>(out);
    cvtw_kernel<1><<<(27 * 128 * kC  + 255) / 256, 256>>>(c1w);
    cvtw_kernel<2><<<(27 * 128 * kCO + 255) / 256, 256>>>(c2w);
    row_kernel<<<kN, 256>>>(feats, n1w, n1b, sdw, sdb, subdiv_out);
    compact_kernel<<<kM / 256, 256>>>();
    skip_kernel<<<kN / 32, 256>>>(feats, skw, skb);
    scatter_kernel<<<kM / 256, 256>>>(coords);
    nidx_kernel<<<kM / 256, 256>>>(coords);
    tap_count_kernel<1><<<27, 256>>>();
    tap_count_kernel<2><<<27, 256>>>();
    tap_scan_kernel<<<1, 32>>>();
    tap_fill_kernel<1><<<27, 256>>>();
    tap_fill_kernel<2><<<27, 256>>>();
    tapgemm_mma<1><<<27 * 128, 256>>>(nullptr);
    h1_ep_kernel<<<kM, 128>>>(c1b);
    tapgemm_mma<2><<<27 * 128, 256>>>(out);
    out_ep_kernel<<<kM, 128>>>(out, c2b);
}

// round 8
// speedup vs baseline: 7.1226x; 1.2256x over previous
#include <cuda_runtime.h>
#include <cuda_bf16.h>
#include <math.h>

// ---------------- problem constants ----------------
constexpr int kN  = 2048;
constexpr int kC  = 256;
constexpr int kCO = 128;
constexpr int kM  = 8 * kN;      // 16384
constexpr int kG  = 66;
constexpr int kG3 = kG * kG * kG;

// ---------------- scratch globals (NEVER passed as kernel args from host) ----
__device__ __nv_bfloat16 g_hhi [(kN + 1) * kC];
__device__ __nv_bfloat16 g_hlo [(kN + 1) * kC];
__device__ __nv_bfloat16 g_h1hi[(kM + 1) * kCO];
__device__ __nv_bfloat16 g_h1lo[(kM + 1) * kCO];
__device__ float g_h1acc[kM * kCO];
__device__ float g_skip [kN * kCO];
__device__ int   g_grid[kG3];
__device__ int   g_nidx [kM * 27];
__device__ int   g_nidx1[kM * 27];
__device__ int   g_mask[kM];
__device__ int   g_cnt;
__device__ int   g_list[kM];
__device__ int   g_in1 [kM * 27 + 27 * 128], g_out1[kM * 27 + 27 * 128];
__device__ int   g_in2 [kM * 27 + 27 * 128], g_out2[kM * 27 + 27 * 128];
__device__ int   g_cnt1[27], g_start1[27], g_plen1[27];
__device__ int   g_cnt2[27], g_start2[27], g_plen2[27];
// transposed bf16 weights: [27][128(n)][CIN(c)]
__device__ __nv_bfloat16 g_w1hi[27 * 128 * kC],  g_w1lo[27 * 128 * kC];
__device__ __nv_bfloat16 g_w2hi[27 * 128 * kCO], g_w2lo[27 * 128 * kCO];

// ---------------- ptx helpers ----------------
__device__ __forceinline__ unsigned smem_u32(const void* p) {
    unsigned a;
    asm("{ .reg .u64 t; cvta.to.shared.u64 t, %1; cvt.u32.u64 %0, t; }"
        : "=r"(a) : "l"(p));
    return a;
}
__device__ __forceinline__ unsigned lds_u32(unsigned addr) {
    unsigned v;
    asm volatile("ld.shared.b32 %0, [%1];" : "=r"(v) : "r"(addr));
    return v;
}
__device__ __forceinline__ void mma16816(float* d, const unsigned* a,
                                         const unsigned* b) {
    asm volatile(
        "mma.sync.aligned.m16n8k16.row.col.f32.bf16.bf16.f32 "
        "{%0,%1,%2,%3}, {%4,%5,%6,%7}, {%8,%9}, {%0,%1,%2,%3};"
        : "+f"(d[0]), "+f"(d[1]), "+f"(d[2]), "+f"(d[3])
        : "r"(a[0]), "r"(a[1]), "r"(a[2]), "r"(a[3]), "r"(b[0]), "r"(b[1]));
}
__device__ __forceinline__ void red_v2(float* p, float a, float b) {
    asm volatile("red.global.add.v2.f32 [%0], {%1, %2};"
                 :: "l"(p), "f"(a), "f"(b) : "memory");
}

// ---------------- fused prep: zero + weight cvt/transpose + grid + scatter ---
constexpr int PB0 = (kM * kCO) / 256;          // 8192  zero h1acc/out
constexpr int PB1 = (27 * 128 * kC) / 256;     // 3456  cvt w1
constexpr int PB2 = (27 * 128 * kCO) / 256;    // 1728  cvt w2
constexpr int PB3 = (kG3 + 255) / 256;         // 1124  grid sentinel
constexpr int PB4 = kM / 256;                  // 64    scatter
constexpr int PREP_BLOCKS = PB0 + PB1 + PB2 + PB3 + PB4 + 1;

__global__ void prep_kernel(float* __restrict__ out,
                            const float* __restrict__ c1w,
                            const float* __restrict__ c2w,
                            const int* __restrict__ coords) {
    const int b = blockIdx.x, t = threadIdx.x;
    if (b < PB0) {
        int i = b * 256 + t;
        g_h1acc[i] = 0.f;
        out[i] = 0.f;
    } else if (b < PB0 + PB1) {
        int idx = (b - PB0) * 256 + t;                // 27*128*256
        int c = idx % kC, n = (idx / kC) & 127, k = idx / (kC * 128);
        float v = c1w[(size_t)k * kC * 128 + (size_t)c * 128 + n];
        __nv_bfloat16 h = __float2bfloat16(v);
        g_w1hi[idx] = h;
        g_w1lo[idx] = __float2bfloat16(v - __bfloat162float(h));
    } else if (b < PB0 + PB1 + PB2) {
        int idx = (b - PB0 - PB1) * 256 + t;          // 27*128*128
        int c = idx % kCO, n = (idx / kCO) & 127, k = idx / (kCO * 128);
        float v = c2w[(size_t)k * kCO * 128 + (size_t)c * 128 + n];
        __nv_bfloat16 h = __float2bfloat16(v);
        g_w2hi[idx] = h;
        g_w2lo[idx] = __float2bfloat16(v - __bfloat162float(h));
    } else if (b < PB0 + PB1 + PB2 + PB3) {
        int i = (b - PB0 - PB1 - PB2) * 256 + t;
        if (i < kG3) g_grid[i] = kM;
    } else if (b < PB0 + PB1 + PB2 + PB3 + PB4) {
        int m = (b - PB0 - PB1 - PB2 - PB3) * 256 + t;
        int n = m >> 3, j = m & 7;
        int cx = coords[n * 3 + 0] * 2 + ((j >> 2) & 1);
        int cy = coords[n * 3 + 1] * 2 + ((j >> 1) & 1);
        int cz = coords[n * 3 + 2] * 2 + (j & 1);
        g_grid[((cx + 1) * kG + (cy + 1)) * kG + (cz + 1)] = m;
    } else {
        if (t < kC)  { g_hhi[kN * kC + t] = __float2bfloat16(0.f);
                       g_hlo[kN * kC + t] = __float2bfloat16(0.f); }
        if (t < kCO) { g_h1hi[kM * kCO + t] = __float2bfloat16(0.f);
                       g_h1lo[kM * kCO + t] = __float2bfloat16(0.f); }
        if (t == 0)  g_cnt = 0;
        if (t < 27)  { g_cnt1[t] = 0; g_cnt2[t] = 0; }
    }
}

// ---------------- per-parent: subdiv + mask + compact + LN + SiLU ------------
__global__ void row_kernel(const float* __restrict__ feats,
                           const float* __restrict__ n1w,
                           const float* __restrict__ n1b,
                           const float* __restrict__ sdw,
                           const float* __restrict__ sdb,
                           float* __restrict__ subdiv_out) {
    const int n = blockIdx.x;
    const int t = threadIdx.x;           // 256
    const int wid = t >> 5, lane = t & 31;
    __shared__ float sf[kC];
    __shared__ float red[8];
    __shared__ int   s_act[8];

    float x = feats[n * kC + t];
    sf[t] = x;
    __syncthreads();

    {
        float p = 0.f;
        #pragma unroll
        for (int i = 0; i < 8; ++i) {
            int c = lane + i * 32;
            p += sf[c] * sdw[c * 8 + wid];
        }
        #pragma unroll
        for (int o = 16; o; o >>= 1) p += __shfl_xor_sync(0xffffffffu, p, o);
        if (lane == 0) {
            p += sdb[wid];
            subdiv_out[n * 8 + wid] = p;
            int act = (p > 0.f) ? 1 : 0;
            g_mask[n * 8 + wid] = act;
            s_act[wid] = act;
        }
    }

    float s = x;
    #pragma unroll
    for (int o = 16; o; o >>= 1) s += __shfl_xor_sync(0xffffffffu, s, o);
    if (lane == 0) red[wid] = s;
    __syncthreads();

    // warp 0: block-local compaction of this parent-block's 8 children
    if (wid == 0) {
        bool act = (lane < 8) && (s_act[lane] != 0);
        unsigned ball = __ballot_sync(0xffffffffu, act);
        int c = __popc(ball);
        int base = 0;
        if (lane == 0 && c) base = atomicAdd(&g_cnt, c);
        base = __shfl_sync(0xffffffffu, base, 0);
        if (act) g_list[base + __popc(ball & ((1u << lane) - 1u))] = n * 8 + lane;
    }

    float tot = 0.f;
    #pragma unroll
    for (int i = 0; i < 8; ++i) tot += red[i];
    const float mean = tot * (1.f / kC);
    const float d = x - mean;
    float s2 = d * d;
    #pragma unroll
    for (int o = 16; o; o >>= 1) s2 += __shfl_xor_sync(0xffffffffu, s2, o);
    __syncthreads();
    if (lane == 0) red[wid] = s2;
    __syncthreads();
    float vtot = 0.f;
    #pragma unroll
    for (int i = 0; i < 8; ++i) vtot += red[i];
    const float var = vtot * (1.f / kC);
    const float y = d * rsqrtf(var + 1e-6f) * n1w[t] + n1b[t];
    const float h = y / (1.f + expf(-y));
    __nv_bfloat16 hh = __float2bfloat16(h);
    g_hhi[n * kC + t] = hh;
    g_hlo[n * kC + t] = __float2bfloat16(h - __bfloat162float(hh));
}

// ---------------- neighbor table + fused tap counting ----------------
__global__ void nidx_kernel(const int* __restrict__ coords) {
    __shared__ int c1[27], c2[27];
    const int t = threadIdx.x;
    const int lane = t & 31;
    if (t < 27) { c1[t] = 0; c2[t] = 0; }
    __syncthreads();

    int m = blockIdx.x * 256 + t;
    int n = m >> 3, j = m & 7;
    int gx = coords[n * 3 + 0] * 2 + ((j >> 2) & 1) + 1;
    int gy = coords[n * 3 + 1] * 2 + ((j >> 1) & 1) + 1;
    int gz = coords[n * 3 + 2] * 2 + (j & 1) + 1;
    const int msk = g_mask[m];
    #pragma unroll
    for (int k = 0; k < 27; ++k) {
        int dx = k / 9 - 1, dy = (k / 3) % 3 - 1, dz = k % 3 - 1;
        int nb = g_grid[((gx + dx) * kG + (gy + dy)) * kG + (gz + dz)];
        g_nidx[m * 27 + k] = nb;
        int in1 = (nb == kM) ? kN : (g_mask[nb] ? (nb >> 3) : kN);
        g_nidx1[m * 27 + k] = in1;
        unsigned b1 = __ballot_sync(0xffffffffu, in1 != kN);
        unsigned b2 = __ballot_sync(0xffffffffu, msk && (nb != kM));
        if (lane == 0) {
            if (b1) atomicAdd(&c1[k], __popc(b1));
            if (b2) atomicAdd(&c2[k], __popc(b2));
        }
    }
    __syncthreads();
    if (t < 27) {
        if (c1[t]) atomicAdd(&g_cnt1[t], c1[t]);
        if (c2[t]) atomicAdd(&g_cnt2[t], c2[t]);
    }
}

// ---------------- scan: starts + padded lengths ----------------
__global__ void tap_scan_kernel() {
    if (threadIdx.x != 0) return;
    int s1 = 0, s2 = 0;
    for (int k = 0; k < 27; ++k) {
        int c = g_cnt1[k], p = (c + 127) & ~127;
        g_start1[k] = s1; g_plen1[k] = p; s1 += p;
        c = g_cnt2[k]; p = (c + 127) & ~127;
        g_start2[k] = s2; g_plen2[k] = p; s2 += p;
    }
}

// ---------------- fill both pair lists in one launch (54 blocks) -------------
__device__ __forceinline__ bool tap_flag_rt(int mode, int m, int k, int& in_id) {
    if (mode == 1) {
        in_id = g_nidx1[m * 27 + k];
        return in_id != kN;
    } else {
        in_id = g_nidx[m * 27 + k];
        return g_mask[m] && (in_id != kM);
    }
}

__global__ void tap_fill_kernel() {
    const int mode = (blockIdx.x < 27) ? 1 : 2;
    const int k = blockIdx.x % 27;
    const int t = threadIdx.x;
    int* __restrict__ pin  = (mode == 1) ? g_in1  : g_in2;
    int* __restrict__ pout = (mode == 1) ? g_out1 : g_out2;
    const int start = (mode == 1 ? g_start1 : g_start2)[k];

    int cnt = 0;
    #pragma unroll 4
    for (int r = 0; r < 64; ++r) {
        int in_id;
        if (tap_flag_rt(mode, t * 64 + r, k, in_id)) ++cnt;
    }
    __shared__ int ex[257];
    ex[t + 1] = cnt;
    __syncthreads();
    if (t == 0) {
        ex[0] = 0;
        for (int i = 0; i < 256; ++i) ex[i + 1] += ex[i];
    }
    __syncthreads();
    int w = start + ex[t];
    for (int r = 0; r < 64; ++r) {
        int m = t * 64 + r, in_id;
        if (tap_flag_rt(mode, m, k, in_id)) {
            pin[w] = in_id;
            pout[w] = m;
            ++w;
        }
    }
    if (t == 0) {
        int tot = ex[256];
        int plen = (mode == 1 ? g_plen1 : g_plen2)[k];
        for (int i = tot; i < plen; ++i) {
            pin[start + i] = (mode == 1) ? kN : kM;   // zero bf16 rows
            pout[start + i] = -1;
        }
    }
}

// ---------------- tensor-core tap GEMM via mma.sync (HMMA) -------------------
// Block tile M=128 x N=128, BK=32, 256 threads (8 warps as 4x2, warp 32x64).
// Register-prefetched global gathers, fragments via plain ld.shared.b32,
// red.v2 scatter epilogue. All device globals selected via MODE template.
template <int MODE>
__global__ void __launch_bounds__(256)
tapgemm_mma(float* __restrict__ ext_out)
{
    constexpr int CIN = (MODE == 1) ? kC : kCO;
    constexpr int BK  = 32;
    constexpr int NCH = CIN / BK;
    constexpr int LDB = 80;                 // tile row stride in bytes (40 bf16)

    __shared__ __align__(16) __nv_bfloat16 Ahi[128 * 40], Alo[128 * 40];
    __shared__ __align__(16) __nv_bfloat16 Bhi[128 * 40], Blo[128 * 40];
    __shared__ int sIdx[128], sOut[128];

    const int k = blockIdx.x >> 7;
    const int s = blockIdx.x & 127;
    const int plen = (MODE == 1 ? g_plen1 : g_plen2)[k];
    if (s * 128 >= plen) return;
    const int base = (MODE == 1 ? g_start1 : g_start2)[k] + s * 128;

    const __nv_bfloat16* __restrict__ shi = (MODE == 1) ? g_hhi : g_h1hi;
    const __nv_bfloat16* __restrict__ slo = (MODE == 1) ? g_hlo : g_h1lo;
    const __nv_bfloat16* __restrict__ whi = (MODE == 1) ? g_w1hi : g_w2hi;
    const __nv_bfloat16* __restrict__ wlo = (MODE == 1) ? g_w1lo : g_w2lo;
    const int* __restrict__ pin  = (MODE == 1) ? g_in1  : g_in2;
    const int* __restrict__ pout = (MODE == 1) ? g_out1 : g_out2;
    float* __restrict__ dstbase  = (MODE == 1) ? g_h1acc : ext_out;

    const int t = threadIdx.x;
    if (t < 128) {
        sIdx[t] = pin[base + t];
        sOut[t] = pout[base + t];
    }
    __syncthreads();

    const unsigned uAhi = smem_u32(Ahi), uAlo = smem_u32(Alo);
    const unsigned uBhi = smem_u32(Bhi), uBlo = smem_u32(Blo);

    const int warp = t >> 5, lane = t & 31;
    const int g = lane >> 2, tid = lane & 3;
    const int wm = (warp & 3) * 32;    // m offset
    const int wn = (warp >> 2) * 64;   // n offset

    float acc[2][8][4];
    #pragma unroll
    for (int i = 0; i < 2; ++i)
        #pragma unroll
        for (int j = 0; j < 8; ++j)
            #pragma unroll
            for (int q = 0; q < 4; ++q) acc[i][j][q] = 0.f;

    const size_t wko = (size_t)k * 128 * CIN;

    // per-thread load coordinates: chunk q0 = t (row t/4), q1 = t+256 (row 64+t/4)
    const int r0 = t >> 2, j0 = t & 3;
    const int r1 = 64 + r0;
    const size_t a0b = (size_t)sIdx[r0] * CIN;
    const size_t a1b = (size_t)sIdx[r1] * CIN;
    const size_t b0b = wko + (size_t)r0 * CIN;
    const size_t b1b = wko + (size_t)r1 * CIN;
    const int to0 = r0 * LDB + j0 * 16;
    const int to1 = r1 * LDB + j0 * 16;

    uint4 pa0h, pa0l, pb0h, pb0l, pa1h, pa1l, pb1h, pb1l;
    {
        pa0h = *((const uint4*)(shi + a0b) + j0);
        pa0l = *((const uint4*)(slo + a0b) + j0);
        pb0h = *((const uint4*)(whi + b0b) + j0);
        pb0l = *((const uint4*)(wlo + b0b) + j0);
        pa1h = *((const uint4*)(shi + a1b) + j0);
        pa1l = *((const uint4*)(slo + a1b) + j0);
        pb1h = *((const uint4*)(whi + b1b) + j0);
        pb1l = *((const uint4*)(wlo + b1b) + j0);
    }

    for (int ch = 0; ch < NCH; ++ch) {
        // ---- stage prefetched chunk into smem ----
        *(uint4*)((char*)Ahi + to0) = pa0h;
        *(uint4*)((char*)Alo + to0) = pa0l;
        *(uint4*)((char*)Bhi + to0) = pb0h;
        *(uint4*)((char*)Blo + to0) = pb0l;
        *(uint4*)((char*)Ahi + to1) = pa1h;
        *(uint4*)((char*)Alo + to1) = pa1l;
        *(uint4*)((char*)Bhi + to1) = pb1h;
        *(uint4*)((char*)Blo + to1) = pb1l;
        __syncthreads();

        // ---- prefetch next chunk (completes during compute) ----
        if (ch + 1 < NCH) {
            const int c0 = (ch + 1) * BK;
            pa0h = *((const uint4*)(shi + a0b + c0) + j0);
            pa0l = *((const uint4*)(slo + a0b + c0) + j0);
            pb0h = *((const uint4*)(whi + b0b + c0) + j0);
            pb0l = *((const uint4*)(wlo + b0b + c0) + j0);
            pa1h = *((const uint4*)(shi + a1b + c0) + j0);
            pa1l = *((const uint4*)(slo + a1b + c0) + j0);
            pb1h = *((const uint4*)(whi + b1b + c0) + j0);
            pb1l = *((const uint4*)(wlo + b1b + c0) + j0);
        }

        // ---- compute (identical to validated round-7 body) ----
        #pragma unroll
        for (int ks = 0; ks < BK / 16; ++ks) {
            const int kb0 = (ks * 16 + 2 * tid) * 2;
            const int kb1 = kb0 + 16;
            unsigned ah[2][4], al[2][4];
            #pragma unroll
            for (int mt = 0; mt < 2; ++mt) {
                int q0 = (wm + mt * 16 + g) * LDB;
                int q1 = q0 + 8 * LDB;
                ah[mt][0] = lds_u32(uAhi + q0 + kb0);
                ah[mt][1] = lds_u32(uAhi + q1 + kb0);
                ah[mt][2] = lds_u32(uAhi + q0 + kb1);
                ah[mt][3] = lds_u32(uAhi + q1 + kb1);
                al[mt][0] = lds_u32(uAlo + q0 + kb0);
                al[mt][1] = lds_u32(uAlo + q1 + kb0);
                al[mt][2] = lds_u32(uAlo + q0 + kb1);
                al[mt][3] = lds_u32(uAlo + q1 + kb1);
            }
            #pragma unroll
            for (int na = 0; na < 8; ++na) {
                int nr = (wn + na * 8 + g) * LDB;
                unsigned bh[2], bl[2];
                bh[0] = lds_u32(uBhi + nr + kb0);
                bh[1] = lds_u32(uBhi + nr + kb1);
                bl[0] = lds_u32(uBlo + nr + kb0);
                bl[1] = lds_u32(uBlo + nr + kb1);
                #pragma unroll
                for (int mt = 0; mt < 2; ++mt) {
                    mma16816(acc[mt][na], ah[mt], bh);
                    mma16816(acc[mt][na], ah[mt], bl);
                    mma16816(acc[mt][na], al[mt], bh);
                }
            }
        }
        __syncthreads();
    }

    // ---- vectorized atomic scatter (c pairs are contiguous columns) ----
    const int cq = tid * 2;
    #pragma unroll
    for (int mt = 0; mt < 2; ++mt) {
        #pragma unroll
        for (int half = 0; half < 2; ++half) {
            int m = wm + mt * 16 + g + half * 8;
            int orow = sOut[m];
            if (orow < 0) continue;
            float* dst = dstbase + (size_t)orow * kCO + wn + cq;
            #pragma unroll
            for (int na = 0; na < 8; ++na)
                red_v2(dst + na * 8, acc[mt][na][half * 2],
                                     acc[mt][na][half * 2 + 1]);
        }
    }
}

// ---------------- skip GEMM (fp32 SIMT, TM=16 -> 128 blocks) ----------------
__global__ void __launch_bounds__(256)
skip_kernel(const float* __restrict__ feats,
            const float* __restrict__ w,
            const float* __restrict__ bias)
{
    constexpr int TM = 16, TK = 32, CIN = kC;
    __shared__ float Ws[TK * 128];
    __shared__ float Gs[TK][TM + 1];
    const int m0 = blockIdx.x * TM;
    const int t = threadIdx.x;

    float acc[8];
    #pragma unroll
    for (int j = 0; j < 8; ++j) acc[j] = 0.f;

    const int tr = t >> 4;          // 0..15
    const int tc = (t & 15) << 3;   // 0..120

    #pragma unroll 1
    for (int c0 = 0; c0 < CIN; c0 += TK) {
        {
            const float4* wsrc = (const float4*)(w + c0 * 128);
            float4* wdst = (float4*)Ws;
            #pragma unroll
            for (int i = 0; i < 4; ++i)
                wdst[t + i * 256] = wsrc[t + i * 256];
        }
        {
            const int c = t & 31;
            #pragma unroll
            for (int i = 0; i < 2; ++i) {
                int r = (t >> 5) + i * 8;
                Gs[c][r] = feats[(size_t)(m0 + r) * CIN + c0 + c];
            }
        }
        __syncthreads();
        #pragma unroll
        for (int kk = 0; kk < TK; ++kk) {
            float a0 = Gs[kk][tr];
            float4 b0 = *(const float4*)&Ws[kk * 128 + tc];
            float4 b1 = *(const float4*)&Ws[kk * 128 + tc + 4];
            float bv[8] = {b0.x, b0.y, b0.z, b0.w, b1.x, b1.y, b1.z, b1.w};
            #pragma unroll
            for (int j = 0; j < 8; ++j)
                acc[j] = fmaf(a0, bv[j], acc[j]);
        }
        __syncthreads();
    }
    int m = m0 + tr;
    #pragma unroll
    for (int j = 0; j < 8; ++j)
        g_skip[(size_t)m * kCO + tc + j] = acc[j] + bias[tc + j];
}

// ---------------- h1 epilogue: +bias -> LN -> SiLU -> bf16 hi/lo -------------
__global__ void h1_ep_kernel(const float* __restrict__ c1b) {
    const int m = blockIdx.x, t = threadIdx.x;   // 128
    const int wid = t >> 5, lane = t & 31;
    __shared__ float red[4];
    float x = g_h1acc[m * kCO + t] + c1b[t];
    float s = x;
    #pragma unroll
    for (int o = 16; o; o >>= 1) s += __shfl_xor_sync(0xffffffffu, s, o);
    if (lane == 0) red[wid] = s;
    __syncthreads();
    const float mean = (red[0] + red[1] + red[2] + red[3]) * (1.f / kCO);
    const float d = x - mean;
    float s2 = d * d;
    #pragma unroll
    for (int o = 16; o; o >>= 1) s2 += __shfl_xor_sync(0xffffffffu, s2, o);
    __syncthreads();
    if (lane == 0) red[wid] = s2;
    __syncthreads();
    const float var = (red[0] + red[1] + red[2] + red[3]) * (1.f / kCO);
    const float y = d * rsqrtf(var + 1e-6f);
    const float h = y / (1.f + expf(-y));
    __nv_bfloat16 hh = __float2bfloat16(h);
    g_h1hi[m * kCO + t] = hh;
    g_h1lo[m * kCO + t] = __float2bfloat16(h - __bfloat162float(hh));
}

// ---------------- out epilogue: += bias + skip (active rows) -----------------
__global__ void out_ep_kernel(float* __restrict__ out,
                              const float* __restrict__ c2b) {
    if ((int)blockIdx.x >= g_cnt) return;
    const int m = g_list[blockIdx.x], t = threadIdx.x;   // 128
    out[(size_t)m * kCO + t] += c2b[t] + g_skip[(size_t)(m >> 3) * kCO + t];
}

// ---------------- launch (ONLY harness pointers cross the boundary) ----------
extern "C" void kernel_launch(void* const* d_in, const int* in_sizes, int n_in,
                              void* d_out, int out_size)
{
    const float* feats = (const float*)d_in[0];
    const float* n1w   = (const float*)d_in[1];
    const float* n1b   = (const float*)d_in[2];
    const float* sdw   = (const float*)d_in[3];
    const float* sdb   = (const float*)d_in[4];
    const float* c1w   = (const float*)d_in[5];
    const float* c1b   = (const float*)d_in[6];
    const float* c2w   = (const float*)d_in[7];
    const float* c2b   = (const float*)d_in[8];
    const float* skw   = (const float*)d_in[9];
    const float* skb   = (const float*)d_in[10];
    const int*   coords= (const int*)d_in[11];

    float* out        = (float*)d_out;
    float* subdiv_out = out + (size_t)kM * kCO;

    prep_kernel<<<PREP_BLOCKS, 256>>>(out, c1w, c2w, coords);
    row_kernel<<<kN, 256>>>(feats, n1w, n1b, sdw, sdb, subdiv_out);
    skip_kernel<<<kN / 16, 256>>>(feats, skw, skb);
    nidx_kernel<<<kM / 256, 256>>>(coords);
    tap_scan_kernel<<<1, 32>>>();
    tap_fill_kernel<<<54, 256>>>();
    tapgemm_mma<1><<<27 * 128, 256>>>(nullptr);
    h1_ep_kernel<<<kM, 128>>>(c1b);
    tapgemm_mma<2><<<27 * 128, 256>>>(out);
    out_ep_kernel<<<kM, 128>>>(out, c2b);
}

// round 9
// speedup vs baseline: 7.4219x; 1.0420x over previous
#include <cuda_runtime.h>
#include <cuda_bf16.h>
#include <math.h>

// ---------------- problem constants ----------------
constexpr int kN  = 2048;
constexpr int kC  = 256;
constexpr int kCO = 128;
constexpr int kM  = 8 * kN;      // 16384
constexpr int kG  = 66;
constexpr int kG3 = kG * kG * kG;

// ---------------- scratch globals (NEVER passed as kernel args from host) ----
__device__ __nv_bfloat16 g_hhi [(kN + 1) * kC];
__device__ __nv_bfloat16 g_hlo [(kN + 1) * kC];
__device__ __nv_bfloat16 g_h1hi[(kM + 1) * kCO];
__device__ __nv_bfloat16 g_h1lo[(kM + 1) * kCO];
__device__ float g_h1acc[kM * kCO];
__device__ float g_skip [kN * kCO];
__device__ int   g_grid[kG3];
__device__ int   g_nidx [kM * 27];
__device__ int   g_nidx1[kM * 27];
__device__ int   g_mask[kM];
__device__ int   g_cnt;
__device__ int   g_list[kM];
__device__ int   g_in1 [kM * 27 + 27 * 128], g_out1[kM * 27 + 27 * 128];
__device__ int   g_in2 [kM * 27 + 27 * 128], g_out2[kM * 27 + 27 * 128];
__device__ int   g_cnt1[27], g_start1[27], g_plen1[27];
__device__ int   g_cnt2[27], g_start2[27], g_plen2[27];
// transposed bf16 weights: [27][128(n)][CIN(c)]
__device__ __nv_bfloat16 g_w1hi[27 * 128 * kC],  g_w1lo[27 * 128 * kC];
__device__ __nv_bfloat16 g_w2hi[27 * 128 * kCO], g_w2lo[27 * 128 * kCO];

// ---------------- ptx helpers ----------------
__device__ __forceinline__ unsigned smem_u32(const void* p) {
    unsigned a;
    asm("{ .reg .u64 t; cvta.to.shared.u64 t, %1; cvt.u32.u64 %0, t; }"
        : "=r"(a) : "l"(p));
    return a;
}
__device__ __forceinline__ void ldsm4(unsigned* r, unsigned addr) {
    asm volatile("ldmatrix.sync.aligned.m8n8.x4.shared.b16 {%0,%1,%2,%3}, [%4];"
                 : "=r"(r[0]), "=r"(r[1]), "=r"(r[2]), "=r"(r[3]) : "r"(addr));
}
__device__ __forceinline__ void mma16816(float* d, const unsigned* a,
                                         const unsigned* b) {
    asm volatile(
        "mma.sync.aligned.m16n8k16.row.col.f32.bf16.bf16.f32 "
        "{%0,%1,%2,%3}, {%4,%5,%6,%7}, {%8,%9}, {%0,%1,%2,%3};"
        : "+f"(d[0]), "+f"(d[1]), "+f"(d[2]), "+f"(d[3])
        : "r"(a[0]), "r"(a[1]), "r"(a[2]), "r"(a[3]), "r"(b[0]), "r"(b[1]));
}
__device__ __forceinline__ void red_v2(float* p, float a, float b) {
    asm volatile("red.global.add.v2.f32 [%0], {%1, %2};"
                 :: "l"(p), "f"(a), "f"(b) : "memory");
}

// ---------------- fused prep: zero + weight cvt/transpose + grid + scatter ---
constexpr int PB0 = (kM * kCO) / 256;          // 8192  zero h1acc/out
constexpr int PB1 = (27 * 128 * kC) / 256;     // 3456  cvt w1
constexpr int PB2 = (27 * 128 * kCO) / 256;    // 1728  cvt w2
constexpr int PB3 = (kG3 + 255) / 256;         // 1124  grid sentinel
constexpr int PB4 = kM / 256;                  // 64    scatter
constexpr int PREP_BLOCKS = PB0 + PB1 + PB2 + PB3 + PB4 + 1;

__global__ void prep_kernel(float* __restrict__ out,
                            const float* __restrict__ c1w,
                            const float* __restrict__ c2w,
                            const int* __restrict__ coords) {
    const int b = blockIdx.x, t = threadIdx.x;
    if (b < PB0) {
        int i = b * 256 + t;
        g_h1acc[i] = 0.f;
        out[i] = 0.f;
    } else if (b < PB0 + PB1) {
        int idx = (b - PB0) * 256 + t;                // 27*128*256
        int c = idx % kC, n = (idx / kC) & 127, k = idx / (kC * 128);
        float v = c1w[(size_t)k * kC * 128 + (size_t)c * 128 + n];
        __nv_bfloat16 h = __float2bfloat16(v);
        g_w1hi[idx] = h;
        g_w1lo[idx] = __float2bfloat16(v - __bfloat162float(h));
    } else if (b < PB0 + PB1 + PB2) {
        int idx = (b - PB0 - PB1) * 256 + t;          // 27*128*128
        int c = idx % kCO, n = (idx / kCO) & 127, k = idx / (kCO * 128);
        float v = c2w[(size_t)k * kCO * 128 + (size_t)c * 128 + n];
        __nv_bfloat16 h = __float2bfloat16(v);
        g_w2hi[idx] = h;
        g_w2lo[idx] = __float2bfloat16(v - __bfloat162float(h));
    } else if (b < PB0 + PB1 + PB2 + PB3) {
        int i = (b - PB0 - PB1 - PB2) * 256 + t;
        if (i < kG3) g_grid[i] = kM;
    } else if (b < PB0 + PB1 + PB2 + PB3 + PB4) {
        int m = (b - PB0 - PB1 - PB2 - PB3) * 256 + t;
        int n = m >> 3, j = m & 7;
        int cx = coords[n * 3 + 0] * 2 + ((j >> 2) & 1);
        int cy = coords[n * 3 + 1] * 2 + ((j >> 1) & 1);
        int cz = coords[n * 3 + 2] * 2 + (j & 1);
        g_grid[((cx + 1) * kG + (cy + 1)) * kG + (cz + 1)] = m;
    } else {
        if (t < kC)  { g_hhi[kN * kC + t] = __float2bfloat16(0.f);
                       g_hlo[kN * kC + t] = __float2bfloat16(0.f); }
        if (t < kCO) { g_h1hi[kM * kCO + t] = __float2bfloat16(0.f);
                       g_h1lo[kM * kCO + t] = __float2bfloat16(0.f); }
        if (t == 0)  g_cnt = 0;
        if (t < 27)  { g_cnt1[t] = 0; g_cnt2[t] = 0; }
    }
}

// ---------------- per-parent: subdiv + mask + compact + LN + SiLU ------------
__global__ void row_kernel(const float* __restrict__ feats,
                           const float* __restrict__ n1w,
                           const float* __restrict__ n1b,
                           const float* __restrict__ sdw,
                           const float* __restrict__ sdb,
                           float* __restrict__ subdiv_out) {
    const int n = blockIdx.x;
    const int t = threadIdx.x;           // 256
    const int wid = t >> 5, lane = t & 31;
    __shared__ float sf[kC];
    __shared__ float red[8];
    __shared__ int   s_act[8];

    float x = feats[n * kC + t];
    sf[t] = x;
    __syncthreads();

    {
        float p = 0.f;
        #pragma unroll
        for (int i = 0; i < 8; ++i) {
            int c = lane + i * 32;
            p += sf[c] * sdw[c * 8 + wid];
        }
        #pragma unroll
        for (int o = 16; o; o >>= 1) p += __shfl_xor_sync(0xffffffffu, p, o);
        if (lane == 0) {
            p += sdb[wid];
            subdiv_out[n * 8 + wid] = p;
            int act = (p > 0.f) ? 1 : 0;
            g_mask[n * 8 + wid] = act;
            s_act[wid] = act;
        }
    }

    float s = x;
    #pragma unroll
    for (int o = 16; o; o >>= 1) s += __shfl_xor_sync(0xffffffffu, s, o);
    if (lane == 0) red[wid] = s;
    __syncthreads();

    if (wid == 0) {
        bool act = (lane < 8) && (s_act[lane] != 0);
        unsigned ball = __ballot_sync(0xffffffffu, act);
        int c = __popc(ball);
        int base = 0;
        if (lane == 0 && c) base = atomicAdd(&g_cnt, c);
        base = __shfl_sync(0xffffffffu, base, 0);
        if (act) g_list[base + __popc(ball & ((1u << lane) - 1u))] = n * 8 + lane;
    }

    float tot = 0.f;
    #pragma unroll
    for (int i = 0; i < 8; ++i) tot += red[i];
    const float mean = tot * (1.f / kC);
    const float d = x - mean;
    float s2 = d * d;
    #pragma unroll
    for (int o = 16; o; o >>= 1) s2 += __shfl_xor_sync(0xffffffffu, s2, o);
    __syncthreads();
    if (lane == 0) red[wid] = s2;
    __syncthreads();
    float vtot = 0.f;
    #pragma unroll
    for (int i = 0; i < 8; ++i) vtot += red[i];
    const float var = vtot * (1.f / kC);
    const float y = d * rsqrtf(var + 1e-6f) * n1w[t] + n1b[t];
    const float h = y / (1.f + expf(-y));
    __nv_bfloat16 hh = __float2bfloat16(h);
    g_hhi[n * kC + t] = hh;
    g_hlo[n * kC + t] = __float2bfloat16(h - __bfloat162float(hh));
}

// ---------------- neighbor table + fused tap counting (64 x 9 blocks) --------
__global__ void nidx_kernel(const int* __restrict__ coords) {
    __shared__ int c1[3], c2[3];
    const int t = threadIdx.x;
    const int lane = t & 31;
    const int k0 = blockIdx.y * 3;
    if (t < 3) { c1[t] = 0; c2[t] = 0; }
    __syncthreads();

    int m = blockIdx.x * 256 + t;
    int n = m >> 3, j = m & 7;
    int gx = coords[n * 3 + 0] * 2 + ((j >> 2) & 1) + 1;
    int gy = coords[n * 3 + 1] * 2 + ((j >> 1) & 1) + 1;
    int gz = coords[n * 3 + 2] * 2 + (j & 1) + 1;
    const int msk = g_mask[m];
    #pragma unroll
    for (int kk = 0; kk < 3; ++kk) {
        int k = k0 + kk;
        int dx = k / 9 - 1, dy = (k / 3) % 3 - 1, dz = k % 3 - 1;
        int nb = g_grid[((gx + dx) * kG + (gy + dy)) * kG + (gz + dz)];
        g_nidx[m * 27 + k] = nb;
        int in1 = (nb == kM) ? kN : (g_mask[nb] ? (nb >> 3) : kN);
        g_nidx1[m * 27 + k] = in1;
        unsigned b1 = __ballot_sync(0xffffffffu, in1 != kN);
        unsigned b2 = __ballot_sync(0xffffffffu, msk && (nb != kM));
        if (lane == 0) {
            if (b1) atomicAdd(&c1[kk], __popc(b1));
            if (b2) atomicAdd(&c2[kk], __popc(b2));
        }
    }
    __syncthreads();
    if (t < 3) {
        if (c1[t]) atomicAdd(&g_cnt1[k0 + t], c1[t]);
        if (c2[t]) atomicAdd(&g_cnt2[k0 + t], c2[t]);
    }
}

// ---------------- scan: starts + padded lengths ----------------
__global__ void tap_scan_kernel() {
    if (threadIdx.x != 0) return;
    int s1 = 0, s2 = 0;
    for (int k = 0; k < 27; ++k) {
        int c = g_cnt1[k], p = (c + 127) & ~127;
        g_start1[k] = s1; g_plen1[k] = p; s1 += p;
        c = g_cnt2[k]; p = (c + 127) & ~127;
        g_start2[k] = s2; g_plen2[k] = p; s2 += p;
    }
}

// ---------------- fill both pair lists in one launch (54 blocks) -------------
__device__ __forceinline__ bool tap_flag_rt(int mode, int m, int k, int& in_id) {
    if (mode == 1) {
        in_id = g_nidx1[m * 27 + k];
        return in_id != kN;
    } else {
        in_id = g_nidx[m * 27 + k];
        return g_mask[m] && (in_id != kM);
    }
}

__global__ void tap_fill_kernel() {
    const int mode = (blockIdx.x < 27) ? 1 : 2;
    const int k = blockIdx.x % 27;
    const int t = threadIdx.x;
    int* __restrict__ pin  = (mode == 1) ? g_in1  : g_in2;
    int* __restrict__ pout = (mode == 1) ? g_out1 : g_out2;
    const int start = (mode == 1 ? g_start1 : g_start2)[k];

    int cnt = 0;
    #pragma unroll 4
    for (int r = 0; r < 64; ++r) {
        int in_id;
        if (tap_flag_rt(mode, t * 64 + r, k, in_id)) ++cnt;
    }
    __shared__ int ex[257];
    ex[t + 1] = cnt;
    __syncthreads();
    if (t == 0) {
        ex[0] = 0;
        for (int i = 0; i < 256; ++i) ex[i + 1] += ex[i];
    }
    __syncthreads();
    int w = start + ex[t];
    for (int r = 0; r < 64; ++r) {
        int m = t * 64 + r, in_id;
        if (tap_flag_rt(mode, m, k, in_id)) {
            pin[w] = in_id;
            pout[w] = m;
            ++w;
        }
    }
    if (t == 0) {
        int tot = ex[256];
        int plen = (mode == 1 ? g_plen1 : g_plen2)[k];
        for (int i = tot; i < plen; ++i) {
            pin[start + i] = (mode == 1) ? kN : kM;   // zero bf16 rows
            pout[start + i] = -1;
        }
    }
}

// ---------------- tensor-core tap GEMM via mma.sync + ldmatrix ---------------
// Block tile M=128 x N=128, BK=32, 256 threads (8 warps as 4x2, warp 32x64).
// Register-prefetched global gathers, ldmatrix.x4 fragment loads (LDB=80 rows
// are bank-conflict-free), red.v2 scatter. Globals selected via MODE template.
template <int MODE>
__global__ void __launch_bounds__(256)
tapgemm_mma(float* __restrict__ ext_out)
{
    constexpr int CIN = (MODE == 1) ? kC : kCO;
    constexpr int BK  = 32;
    constexpr int NCH = CIN / BK;
    constexpr int LDB = 80;                 // tile row stride in bytes (40 bf16)

    __shared__ __align__(16) __nv_bfloat16 Ahi[128 * 40], Alo[128 * 40];
    __shared__ __align__(16) __nv_bfloat16 Bhi[128 * 40], Blo[128 * 40];
    __shared__ int sIdx[128], sOut[128];

    const int k = blockIdx.x >> 7;
    const int s = blockIdx.x & 127;
    const int plen = (MODE == 1 ? g_plen1 : g_plen2)[k];
    if (s * 128 >= plen) return;
    const int base = (MODE == 1 ? g_start1 : g_start2)[k] + s * 128;

    const __nv_bfloat16* __restrict__ shi = (MODE == 1) ? g_hhi : g_h1hi;
    const __nv_bfloat16* __restrict__ slo = (MODE == 1) ? g_hlo : g_h1lo;
    const __nv_bfloat16* __restrict__ whi = (MODE == 1) ? g_w1hi : g_w2hi;
    const __nv_bfloat16* __restrict__ wlo = (MODE == 1) ? g_w1lo : g_w2lo;
    const int* __restrict__ pin  = (MODE == 1) ? g_in1  : g_in2;
    const int* __restrict__ pout = (MODE == 1) ? g_out1 : g_out2;
    float* __restrict__ dstbase  = (MODE == 1) ? g_h1acc : ext_out;

    const int t = threadIdx.x;
    if (t < 128) {
        sIdx[t] = pin[base + t];
        sOut[t] = pout[base + t];
    }
    __syncthreads();

    const unsigned uAhi = smem_u32(Ahi), uAlo = smem_u32(Alo);
    const unsigned uBhi = smem_u32(Bhi), uBlo = smem_u32(Blo);

    const int warp = t >> 5, lane = t & 31;
    const int g = lane >> 2, tid = lane & 3;
    const int wm = (warp & 3) * 32;    // m offset
    const int wn = (warp >> 2) * 64;   // n offset

    // ldmatrix lane addressing (PTX x4 spec):
    // A: sub-matrices = (klo rows 0-15 | khi rows 0-15)
    const int a_row  = lane & 15;
    const int a_koff = (lane >> 4) * 16;               // byte offset in k
    // B: regs {b0,b1} slice n(0-7), {b2,b3} slice n(8-15)
    const int b_row  = (lane & 7) + (lane >> 4) * 8;
    const int b_koff = ((lane >> 3) & 1) * 16;

    float acc[2][8][4];
    #pragma unroll
    for (int i = 0; i < 2; ++i)
        #pragma unroll
        for (int j = 0; j < 8; ++j)
            #pragma unroll
            for (int q = 0; q < 4; ++q) acc[i][j][q] = 0.f;

    const size_t wko = (size_t)k * 128 * CIN;

    const int r0 = t >> 2, j0 = t & 3;
    const int r1 = 64 + r0;
    const size_t a0b = (size_t)sIdx[r0] * CIN;
    const size_t a1b = (size_t)sIdx[r1] * CIN;
    const size_t b0b = wko + (size_t)r0 * CIN;
    const size_t b1b = wko + (size_t)r1 * CIN;
    const int to0 = r0 * LDB + j0 * 16;
    const int to1 = r1 * LDB + j0 * 16;

    uint4 pa0h, pa0l, pb0h, pb0l, pa1h, pa1l, pb1h, pb1l;
    {
        pa0h = *((const uint4*)(shi + a0b) + j0);
        pa0l = *((const uint4*)(slo + a0b) + j0);
        pb0h = *((const uint4*)(whi + b0b) + j0);
        pb0l = *((const uint4*)(wlo + b0b) + j0);
        pa1h = *((const uint4*)(shi + a1b) + j0);
        pa1l = *((const uint4*)(slo + a1b) + j0);
        pb1h = *((const uint4*)(whi + b1b) + j0);
        pb1l = *((const uint4*)(wlo + b1b) + j0);
    }

    for (int ch = 0; ch < NCH; ++ch) {
        *(uint4*)((char*)Ahi + to0) = pa0h;
        *(uint4*)((char*)Alo + to0) = pa0l;
        *(uint4*)((char*)Bhi + to0) = pb0h;
        *(uint4*)((char*)Blo + to0) = pb0l;
        *(uint4*)((char*)Ahi + to1) = pa1h;
        *(uint4*)((char*)Alo + to1) = pa1l;
        *(uint4*)((char*)Bhi + to1) = pb1h;
        *(uint4*)((char*)Blo + to1) = pb1l;
        __syncthreads();

        if (ch + 1 < NCH) {
            const int c0 = (ch + 1) * BK;
            pa0h = *((const uint4*)(shi + a0b + c0) + j0);
            pa0l = *((const uint4*)(slo + a0b + c0) + j0);
            pb0h = *((const uint4*)(whi + b0b + c0) + j0);
            pb0l = *((const uint4*)(wlo + b0b + c0) + j0);
            pa1h = *((const uint4*)(shi + a1b + c0) + j0);
            pa1l = *((const uint4*)(slo + a1b + c0) + j0);
            pb1h = *((const uint4*)(whi + b1b + c0) + j0);
            pb1l = *((const uint4*)(wlo + b1b + c0) + j0);
        }

        #pragma unroll
        for (int ks = 0; ks < BK / 16; ++ks) {
            const int akb = ks * 32 + a_koff;
            const int bkb = ks * 32 + b_koff;
            unsigned ah[2][4], al[2][4];
            #pragma unroll
            for (int mt = 0; mt < 2; ++mt) {
                unsigned aoff = (unsigned)((wm + mt * 16 + a_row) * LDB + akb);
                ldsm4(ah[mt], uAhi + aoff);
                ldsm4(al[mt], uAlo + aoff);
            }
            #pragma unroll
            for (int n2 = 0; n2 < 4; ++n2) {
                unsigned boff = (unsigned)((wn + n2 * 16 + b_row) * LDB + bkb);
                unsigned bh[4], bl[4];
                ldsm4(bh, uBhi + boff);
                ldsm4(bl, uBlo + boff);
                #pragma unroll
                for (int mt = 0; mt < 2; ++mt) {
                    mma16816(acc[mt][n2 * 2],     ah[mt], bh);
                    mma16816(acc[mt][n2 * 2],     ah[mt], bl);
                    mma16816(acc[mt][n2 * 2],     al[mt], bh);
                    mma16816(acc[mt][n2 * 2 + 1], ah[mt], bh + 2);
                    mma16816(acc[mt][n2 * 2 + 1], ah[mt], bl + 2);
                    mma16816(acc[mt][n2 * 2 + 1], al[mt], bh + 2);
                }
            }
        }
        __syncthreads();
    }

    // ---- vectorized atomic scatter ----
    const int cq = tid * 2;
    #pragma unroll
    for (int mt = 0; mt < 2; ++mt) {
        #pragma unroll
        for (int half = 0; half < 2; ++half) {
            int m = wm + mt * 16 + g + half * 8;
            int orow = sOut[m];
            if (orow < 0) continue;
            float* dst = dstbase + (size_t)orow * kCO + wn + cq;
            #pragma unroll
            for (int na = 0; na < 8; ++na)
                red_v2(dst + na * 8, acc[mt][na][half * 2],
                                     acc[mt][na][half * 2 + 1]);
        }
    }
}

// ---------------- skip GEMM (fp32 SIMT, TM=16 -> 128 blocks) ----------------
__global__ void __launch_bounds__(256)
skip_kernel(const float* __restrict__ feats,
            const float* __restrict__ w,
            const float* __restrict__ bias)
{
    constexpr int TM = 16, TK = 32, CIN = kC;
    __shared__ float Ws[TK * 128];
    __shared__ float Gs[TK][TM + 1];
    const int m0 = blockIdx.x * TM;
    const int t = threadIdx.x;

    float acc[8];
    #pragma unroll
    for (int j = 0; j < 8; ++j) acc[j] = 0.f;

    const int tr = t >> 4;
    const int tc = (t & 15) << 3;

    #pragma unroll 1
    for (int c0 = 0; c0 < CIN; c0 += TK) {
        {
            const float4* wsrc = (const float4*)(w + c0 * 128);
            float4* wdst = (float4*)Ws;
            #pragma unroll
            for (int i = 0; i < 4; ++i)
                wdst[t + i * 256] = wsrc[t + i * 256];
        }
        {
            const int c = t & 31;
            #pragma unroll
            for (int i = 0; i < 2; ++i) {
                int r = (t >> 5) + i * 8;
                Gs[c][r] = feats[(size_t)(m0 + r) * CIN + c0 + c];
            }
        }
        __syncthreads();
        #pragma unroll
        for (int kk = 0; kk < TK; ++kk) {
            float a0 = Gs[kk][tr];
            float4 b0 = *(const float4*)&Ws[kk * 128 + tc];
            float4 b1 = *(const float4*)&Ws[kk * 128 + tc + 4];
            float bv[8] = {b0.x, b0.y, b0.z, b0.w, b1.x, b1.y, b1.z, b1.w};
            #pragma unroll
            for (int j = 0; j < 8; ++j)
                acc[j] = fmaf(a0, bv[j], acc[j]);
        }
        __syncthreads();
    }
    int m = m0 + tr;
    #pragma unroll
    for (int j = 0; j < 8; ++j)
        g_skip[(size_t)m * kCO + tc + j] = acc[j] + bias[tc + j];
}

// ---------------- h1 epilogue: +bias -> LN -> SiLU -> bf16 hi/lo -------------
__global__ void h1_ep_kernel(const float* __restrict__ c1b) {
    const int m = blockIdx.x, t = threadIdx.x;   // 128
    const int wid = t >> 5, lane = t & 31;
    __shared__ float red[4];
    float x = g_h1acc[m * kCO + t] + c1b[t];
    float s = x;
    #pragma unroll
    for (int o = 16; o; o >>= 1) s += __shfl_xor_sync(0xffffffffu, s, o);
    if (lane == 0) red[wid] = s;
    __syncthreads();
    const float mean = (red[0] + red[1] + red[2] + red[3]) * (1.f / kCO);
    const float d = x - mean;
    float s2 = d * d;
    #pragma unroll
    for (int o = 16; o; o >>= 1) s2 += __shfl_xor_sync(0xffffffffu, s2, o);
    __syncthreads();
    if (lane == 0) red[wid] = s2;
    __syncthreads();
    const float var = (red[0] + red[1] + red[2] + red[3]) * (1.f / kCO);
    const float y = d * rsqrtf(var + 1e-6f);
    const float h = y / (1.f + expf(-y));
    __nv_bfloat16 hh = __float2bfloat16(h);
    g_h1hi[m * kCO + t] = hh;
    g_h1lo[m * kCO + t] = __float2bfloat16(h - __bfloat162float(hh));
}

// ---------------- out epilogue: += bias + skip (active rows) -----------------
__global__ void out_ep_kernel(float* __restrict__ out,
                              const float* __restrict__ c2b) {
    if ((int)blockIdx.x >= g_cnt) return;
    const int m = g_list[blockIdx.x], t = threadIdx.x;   // 128
    out[(size_t)m * kCO + t] += c2b[t] + g_skip[(size_t)(m >> 3) * kCO + t];
}

// ---------------- launch (ONLY harness pointers cross the boundary) ----------
extern "C" void kernel_launch(void* const* d_in, const int* in_sizes, int n_in,
                              void* d_out, int out_size)
{
    const float* feats = (const float*)d_in[0];
    const float* n1w   = (const float*)d_in[1];
    const float* n1b   = (const float*)d_in[2];
    const float* sdw   = (const float*)d_in[3];
    const float* sdb   = (const float*)d_in[4];
    const float* c1w   = (const float*)d_in[5];
    const float* c1b   = (const float*)d_in[6];
    const float* c2w   = (const float*)d_in[7];
    const float* c2b   = (const float*)d_in[8];
    const float* skw   = (const float*)d_in[9];
    const float* skb   = (const float*)d_in[10];
    const int*   coords= (const int*)d_in[11];

    float* out        = (float*)d_out;
    float* subdiv_out = out + (size_t)kM * kCO;

    prep_kernel<<<PREP_BLOCKS, 256>>>(out, c1w, c2w, coords);
    row_kernel<<<kN, 256>>>(feats, n1w, n1b, sdw, sdb, subdiv_out);
    skip_kernel<<<kN / 16, 256>>>(feats, skw, skb);
    nidx_kernel<<<dim3(kM / 256, 9), 256>>>(coords);
    tap_scan_kernel<<<1, 32>>>();
    tap_fill_kernel<<<54, 256>>>();
    tapgemm_mma<1><<<27 * 128, 256>>>(nullptr);
    h1_ep_kernel<<<kM, 128>>>(c1b);
    tapgemm_mma<2><<<27 * 128, 256>>>(out);
    out_ep_kernel<<<kM, 128>>>(out, c2b);
}

// round 11
// speedup vs baseline: 8.0043x; 1.0785x over previous
#include <cuda_runtime.h>
#include <cuda_bf16.h>
#include <math.h>

// ---------------- problem constants ----------------
constexpr int kN  = 2048;
constexpr int kC  = 256;
constexpr int kCO = 128;
constexpr int kM  = 8 * kN;      // 16384
constexpr int kG  = 66;
constexpr int kG3 = kG * kG * kG;

// ---------------- scratch globals (NEVER passed as kernel args from host) ----
__device__ __nv_bfloat16 g_hhi [(kN + 1) * kC];
__device__ __nv_bfloat16 g_hlo [(kN + 1) * kC];
__device__ __nv_bfloat16 g_h1hi[(kM + 1) * kCO];
__device__ __nv_bfloat16 g_h1lo[(kM + 1) * kCO];
__device__ float g_h1acc[kM * kCO];
__device__ float g_skip [kN * kCO];
__device__ int   g_grid[kG3];
__device__ int   g_nidx [kM * 27];
__device__ int   g_nidx1[kM * 27];
__device__ int   g_mask[kM];
__device__ int   g_cnt;
__device__ int   g_list[kM];
__device__ int   g_in1 [kM * 27 + 27 * 128], g_out1[kM * 27 + 27 * 128];
__device__ int   g_in2 [kM * 27 + 27 * 128], g_out2[kM * 27 + 27 * 128];
__device__ int   g_cnt1[27], g_start1[27], g_plen1[27];
__device__ int   g_cnt2[27], g_start2[27], g_plen2[27];
// transposed bf16 weights: [27][128(n)][CIN(c)]
__device__ __nv_bfloat16 g_w1hi[27 * 128 * kC],  g_w1lo[27 * 128 * kC];
__device__ __nv_bfloat16 g_w2hi[27 * 128 * kCO], g_w2lo[27 * 128 * kCO];

// ---------------- ptx helpers ----------------
__device__ __forceinline__ unsigned smem_u32(const void* p) {
    unsigned a;
    asm("{ .reg .u64 t; cvta.to.shared.u64 t, %1; cvt.u32.u64 %0, t; }"
        : "=r"(a) : "l"(p));
    return a;
}
__device__ __forceinline__ void ldsm4(unsigned* r, unsigned addr) {
    asm volatile("ldmatrix.sync.aligned.m8n8.x4.shared.b16 {%0,%1,%2,%3}, [%4];"
                 : "=r"(r[0]), "=r"(r[1]), "=r"(r[2]), "=r"(r[3]) : "r"(addr));
}
__device__ __forceinline__ void mma16816(float* d, const unsigned* a,
                                         const unsigned* b) {
    asm volatile(
        "mma.sync.aligned.m16n8k16.row.col.f32.bf16.bf16.f32 "
        "{%0,%1,%2,%3}, {%4,%5,%6,%7}, {%8,%9}, {%0,%1,%2,%3};"
        : "+f"(d[0]), "+f"(d[1]), "+f"(d[2]), "+f"(d[3])
        : "r"(a[0]), "r"(a[1]), "r"(a[2]), "r"(a[3]), "r"(b[0]), "r"(b[1]));
}
__device__ __forceinline__ void red_v4(float* p, float4 v) {
    asm volatile("red.global.add.v4.f32 [%0], {%1, %2, %3, %4};"
                 :: "l"(p), "f"(v.x), "f"(v.y), "f"(v.z), "f"(v.w) : "memory");
}

// ---------------- fused prep: zero + coalesced weight transpose + grid -------
// NOTE: the child->grid scatter is a SEPARATE subsequent launch; a sentinel
// write racing a scatter write within one launch silently drops voxels.
constexpr int PB0 = (kM * kCO) / 256;          // 8192  zero h1acc/out
constexpr int PT1 = 27 * 8 * 4;                // 864   w1 32x32 transpose tiles
constexpr int PT2 = 27 * 4 * 4;                // 432   w2 tiles
constexpr int PB3 = (kG3 + 255) / 256;         // 1124  grid sentinel
constexpr int PREP_BLOCKS = PB0 + PT1 + PT2 + PB3 + 1;

__global__ void prep_kernel(float* __restrict__ out,
                            const float* __restrict__ c1w,
                            const float* __restrict__ c2w) {
    __shared__ float sT[32][33];
    const int b = blockIdx.x, t = threadIdx.x;
    if (b < PB0) {
        int i = b * 256 + t;
        g_h1acc[i] = 0.f;
        out[i] = 0.f;
    } else if (b < PB0 + PT1) {
        // w1: [27][256(c)][128(n)] -> [27][128(n)][256(c)], 32x32 tiles
        int b1 = b - PB0;
        int k = b1 >> 5, r = b1 & 31;
        int c0 = (r >> 2) * 32, n0 = (r & 3) * 32;
        const float* wk = c1w + (size_t)k * kC * 128;
        int nx = t & 31, cy = t >> 5;
        #pragma unroll
        for (int i = 0; i < 4; ++i)
            sT[cy + 8 * i][nx] = wk[(size_t)(c0 + cy + 8 * i) * 128 + n0 + nx];
        __syncthreads();
        int cx = t & 31, ny = t >> 5;
        #pragma unroll
        for (int i = 0; i < 4; ++i) {
            float v = sT[cx][ny + 8 * i];
            __nv_bfloat16 h = __float2bfloat16(v);
            size_t o = (size_t)k * 128 * kC + (size_t)(n0 + ny + 8 * i) * kC + c0 + cx;
            g_w1hi[o] = h;
            g_w1lo[o] = __float2bfloat16(v - __bfloat162float(h));
        }
    } else if (b < PB0 + PT1 + PT2) {
        // w2: [27][128(c)][128(n)] -> [27][128(n)][128(c)]
        int b2 = b - PB0 - PT1;
        int k = b2 >> 4, r = b2 & 15;
        int c0 = (r >> 2) * 32, n0 = (r & 3) * 32;
        const float* wk = c2w + (size_t)k * kCO * 128;
        int nx = t & 31, cy = t >> 5;
        #pragma unroll
        for (int i = 0; i < 4; ++i)
            sT[cy + 8 * i][nx] = wk[(size_t)(c0 + cy + 8 * i) * 128 + n0 + nx];
        __syncthreads();
        int cx = t & 31, ny = t >> 5;
        #pragma unroll
        for (int i = 0; i < 4; ++i) {
            float v = sT[cx][ny + 8 * i];
            __nv_bfloat16 h = __float2bfloat16(v);
            size_t o = (size_t)k * 128 * kCO + (size_t)(n0 + ny + 8 * i) * kCO + c0 + cx;
            g_w2hi[o] = h;
            g_w2lo[o] = __float2bfloat16(v - __bfloat162float(h));
        }
    } else if (b < PB0 + PT1 + PT2 + PB3) {
        int i = (b - PB0 - PT1 - PT2) * 256 + t;
        if (i < kG3) g_grid[i] = kM;
    } else {
        if (t < kC)  { g_hhi[kN * kC + t] = __float2bfloat16(0.f);
                       g_hlo[kN * kC + t] = __float2bfloat16(0.f); }
        if (t < kCO) { g_h1hi[kM * kCO + t] = __float2bfloat16(0.f);
                       g_h1lo[kM * kCO + t] = __float2bfloat16(0.f); }
        if (t == 0)  g_cnt = 0;
        if (t < 27)  { g_cnt1[t] = 0; g_cnt2[t] = 0; }
    }
}

// ---------------- child scatter (separate launch: ordered AFTER sentinel) ----
__global__ void scatter_kernel(const int* __restrict__ coords) {
    int m = blockIdx.x * 256 + threadIdx.x;
    int n = m >> 3, j = m & 7;
    int cx = coords[n * 3 + 0] * 2 + ((j >> 2) & 1);
    int cy = coords[n * 3 + 1] * 2 + ((j >> 1) & 1);
    int cz = coords[n * 3 + 2] * 2 + (j & 1);
    g_grid[((cx + 1) * kG + (cy + 1)) * kG + (cz + 1)] = m;
}

// ---------------- per-parent: subdiv + mask + compact + LN + SiLU ------------
__global__ void row_kernel(const float* __restrict__ feats,
                           const float* __restrict__ n1w,
                           const float* __restrict__ n1b,
                           const float* __restrict__ sdw,
                           const float* __restrict__ sdb,
                           float* __restrict__ subdiv_out) {
    const int n = blockIdx.x;
    const int t = threadIdx.x;           // 256
    const int wid = t >> 5, lane = t & 31;
    __shared__ float sf[kC];
    __shared__ float red[8];
    __shared__ int   s_act[8];

    float x = feats[n * kC + t];
    sf[t] = x;
    __syncthreads();

    {
        float p = 0.f;
        #pragma unroll
        for (int i = 0; i < 8; ++i) {
            int c = lane + i * 32;
            p += sf[c] * sdw[c * 8 + wid];
        }
        #pragma unroll
        for (int o = 16; o; o >>= 1) p += __shfl_xor_sync(0xffffffffu, p, o);
        if (lane == 0) {
            p += sdb[wid];
            subdiv_out[n * 8 + wid] = p;
            int act = (p > 0.f) ? 1 : 0;
            g_mask[n * 8 + wid] = act;
            s_act[wid] = act;
        }
    }

    float s = x;
    #pragma unroll
    for (int o = 16; o; o >>= 1) s += __shfl_xor_sync(0xffffffffu, s, o);
    if (lane == 0) red[wid] = s;
    __syncthreads();

    if (wid == 0) {
        bool act = (lane < 8) && (s_act[lane] != 0);
        unsigned ball = __ballot_sync(0xffffffffu, act);
        int c = __popc(ball);
        int base = 0;
        if (lane == 0 && c) base = atomicAdd(&g_cnt, c);
        base = __shfl_sync(0xffffffffu, base, 0);
        if (act) g_list[base + __popc(ball & ((1u << lane) - 1u))] = n * 8 + lane;
    }

    float tot = 0.f;
    #pragma unroll
    for (int i = 0; i < 8; ++i) tot += red[i];
    const float mean = tot * (1.f / kC);
    const float d = x - mean;
    float s2 = d * d;
    #pragma unroll
    for (int o = 16; o; o >>= 1) s2 += __shfl_xor_sync(0xffffffffu, s2, o);
    __syncthreads();
    if (lane == 0) red[wid] = s2;
    __syncthreads();
    float vtot = 0.f;
    #pragma unroll
    for (int i = 0; i < 8; ++i) vtot += red[i];
    const float var = vtot * (1.f / kC);
    const float y = d * rsqrtf(var + 1e-6f) * n1w[t] + n1b[t];
    const float h = y / (1.f + expf(-y));
    __nv_bfloat16 hh = __float2bfloat16(h);
    g_hhi[n * kC + t] = hh;
    g_hlo[n * kC + t] = __float2bfloat16(h - __bfloat162float(hh));
}

// ---------------- neighbor table + fused tap counting (64 x 9 blocks) --------
__global__ void nidx_kernel(const int* __restrict__ coords) {
    __shared__ int c1[3], c2[3];
    const int t = threadIdx.x;
    const int lane = t & 31;
    const int k0 = blockIdx.y * 3;
    if (t < 3) { c1[t] = 0; c2[t] = 0; }
    __syncthreads();

    int m = blockIdx.x * 256 + t;
    int n = m >> 3, j = m & 7;
    int gx = coords[n * 3 + 0] * 2 + ((j >> 2) & 1) + 1;
    int gy = coords[n * 3 + 1] * 2 + ((j >> 1) & 1) + 1;
    int gz = coords[n * 3 + 2] * 2 + (j & 1) + 1;
    const int msk = g_mask[m];
    #pragma unroll
    for (int kk = 0; kk < 3; ++kk) {
        int k = k0 + kk;
        int dx = k / 9 - 1, dy = (k / 3) % 3 - 1, dz = k % 3 - 1;
        int nb = g_grid[((gx + dx) * kG + (gy + dy)) * kG + (gz + dz)];
        g_nidx[m * 27 + k] = nb;
        int in1 = (nb == kM) ? kN : (g_mask[nb] ? (nb >> 3) : kN);
        g_nidx1[m * 27 + k] = in1;
        unsigned b1 = __ballot_sync(0xffffffffu, in1 != kN);
        unsigned b2 = __ballot_sync(0xffffffffu, msk && (nb != kM));
        if (lane == 0) {
            if (b1) atomicAdd(&c1[kk], __popc(b1));
            if (b2) atomicAdd(&c2[kk], __popc(b2));
        }
    }
    __syncthreads();
    if (t < 3) {
        if (c1[t]) atomicAdd(&g_cnt1[k0 + t], c1[t]);
        if (c2[t]) atomicAdd(&g_cnt2[k0 + t], c2[t]);
    }
}

// ---------------- scan: starts + padded lengths ----------------
__global__ void tap_scan_kernel() {
    if (threadIdx.x != 0) return;
    int s1 = 0, s2 = 0;
    for (int k = 0; k < 27; ++k) {
        int c = g_cnt1[k], p = (c + 127) & ~127;
        g_start1[k] = s1; g_plen1[k] = p; s1 += p;
        c = g_cnt2[k]; p = (c + 127) & ~127;
        g_start2[k] = s2; g_plen2[k] = p; s2 += p;
    }
}

// ---------------- fill both pair lists in one launch (54 blocks) -------------
__device__ __forceinline__ bool tap_flag_rt(int mode, int m, int k, int& in_id) {
    if (mode == 1) {
        in_id = g_nidx1[m * 27 + k];
        return in_id != kN;
    } else {
        in_id = g_nidx[m * 27 + k];
        return g_mask[m] && (in_id != kM);
    }
}

__global__ void tap_fill_kernel() {
    const int mode = (blockIdx.x < 27) ? 1 : 2;
    const int k = blockIdx.x % 27;
    const int t = threadIdx.x;
    int* __restrict__ pin  = (mode == 1) ? g_in1  : g_in2;
    int* __restrict__ pout = (mode == 1) ? g_out1 : g_out2;
    const int start = (mode == 1 ? g_start1 : g_start2)[k];

    int cnt = 0;
    #pragma unroll 4
    for (int r = 0; r < 64; ++r) {
        int in_id;
        if (tap_flag_rt(mode, t * 64 + r, k, in_id)) ++cnt;
    }
    // Hillis-Steele inclusive scan over 256 counts
    __shared__ int sh[256];
    sh[t] = cnt;
    __syncthreads();
    #pragma unroll
    for (int off = 1; off < 256; off <<= 1) {
        int u = (t >= off) ? sh[t - off] : 0;
        __syncthreads();
        sh[t] += u;
        __syncthreads();
    }
    int w = start + sh[t] - cnt;      // exclusive prefix
    const int tot = sh[255];
    for (int r = 0; r < 64; ++r) {
        int m = t * 64 + r, in_id;
        if (tap_flag_rt(mode, m, k, in_id)) {
            pin[w] = in_id;
            pout[w] = m;
            ++w;
        }
    }
    const int plen = (mode == 1 ? g_plen1 : g_plen2)[k];
    for (int i = tot + t; i < plen; i += 256) {
        pin[start + i] = (mode == 1) ? kN : kM;   // zero bf16 rows
        pout[start + i] = -1;
    }
}

// ---------------- tensor-core tap GEMM via mma.sync + ldmatrix ---------------
// Block tile M=128 x N=128, BK=32, 256 threads (8 warps as 4x2, warp 32x64).
// Depth-2 register prefetch, ldmatrix.x4 fragments, smem-transposed red.v4
// scatter. Globals selected via MODE template.
template <int MODE>
__global__ void __launch_bounds__(256)
tapgemm_mma(float* __restrict__ ext_out)
{
    constexpr int CIN = (MODE == 1) ? kC : kCO;
    constexpr int BK  = 32;
    constexpr int NCH = CIN / BK;
    constexpr int LDB = 80;                 // tile row stride in bytes (40 bf16)

    // 4 bf16 tiles (40960B) aliased with the fp32 transpose buffer (33792B)
    __shared__ __align__(16) char smem_raw[40960];
    __shared__ int sIdx[128], sOut[128];
    __nv_bfloat16* Ahi = (__nv_bfloat16*)(smem_raw);
    __nv_bfloat16* Alo = (__nv_bfloat16*)(smem_raw + 10240);
    __nv_bfloat16* Bhi = (__nv_bfloat16*)(smem_raw + 20480);
    __nv_bfloat16* Blo = (__nv_bfloat16*)(smem_raw + 30720);
    float* T = (float*)smem_raw;            // 64 x 132 floats

    const int k = blockIdx.x >> 7;
    const int s = blockIdx.x & 127;
    const int plen = (MODE == 1 ? g_plen1 : g_plen2)[k];
    if (s * 128 >= plen) return;
    const int base = (MODE == 1 ? g_start1 : g_start2)[k] + s * 128;

    const __nv_bfloat16* __restrict__ shi = (MODE == 1) ? g_hhi : g_h1hi;
    const __nv_bfloat16* __restrict__ slo = (MODE == 1) ? g_hlo : g_h1lo;
    const __nv_bfloat16* __restrict__ whi = (MODE == 1) ? g_w1hi : g_w2hi;
    const __nv_bfloat16* __restrict__ wlo = (MODE == 1) ? g_w1lo : g_w2lo;
    const int* __restrict__ pin  = (MODE == 1) ? g_in1  : g_in2;
    const int* __restrict__ pout = (MODE == 1) ? g_out1 : g_out2;
    float* __restrict__ dstbase  = (MODE == 1) ? g_h1acc : ext_out;

    const int t = threadIdx.x;
    if (t < 128) {
        sIdx[t] = pin[base + t];
        sOut[t] = pout[base + t];
    }
    __syncthreads();

    const unsigned uAhi = smem_u32(Ahi), uAlo = smem_u32(Alo);
    const unsigned uBhi = smem_u32(Bhi), uBlo = smem_u32(Blo);

    const int warp = t >> 5, lane = t & 31;
    const int g = lane >> 2, tid = lane & 3;
    const int wm = (warp & 3) * 32;    // m offset
    const int wn = (warp >> 2) * 64;   // n offset

    // ldmatrix lane addressing (PTX x4 spec)
    const int a_row  = lane & 15;
    const int a_koff = (lane >> 4) * 16;
    const int b_row  = (lane & 7) + (lane >> 4) * 8;
    const int b_koff = ((lane >> 3) & 1) * 16;

    float acc[2][8][4];
    #pragma unroll
    for (int i = 0; i < 2; ++i)
        #pragma unroll
        for (int j = 0; j < 8; ++j)
            #pragma unroll
            for (int q = 0; q < 4; ++q) acc[i][j][q] = 0.f;

    const size_t wko = (size_t)k * 128 * CIN;

    const int r0 = t >> 2, j0 = t & 3;
    const int r1 = 64 + r0;
    const size_t a0b = (size_t)sIdx[r0] * CIN;
    const size_t a1b = (size_t)sIdx[r1] * CIN;
    const size_t b0b = wko + (size_t)r0 * CIN;
    const size_t b1b = wko + (size_t)r1 * CIN;
    const int to0 = r0 * LDB + j0 * 16;
    const int to1 = r1 * LDB + j0 * 16;

    // depth-2 register prefetch: P[slot][tile 0..7]
    uint4 P[2][8];
    #pragma unroll
    for (int sl = 0; sl < 2; ++sl) {
        const int c0 = sl * BK;
        P[sl][0] = *((const uint4*)(shi + a0b + c0) + j0);
        P[sl][1] = *((const uint4*)(slo + a0b + c0) + j0);
        P[sl][2] = *((const uint4*)(whi + b0b + c0) + j0);
        P[sl][3] = *((const uint4*)(wlo + b0b + c0) + j0);
        P[sl][4] = *((const uint4*)(shi + a1b + c0) + j0);
        P[sl][5] = *((const uint4*)(slo + a1b + c0) + j0);
        P[sl][6] = *((const uint4*)(whi + b1b + c0) + j0);
        P[sl][7] = *((const uint4*)(wlo + b1b + c0) + j0);
    }

    #pragma unroll
    for (int ch = 0; ch < NCH; ++ch) {
        const int sl = ch & 1;
        *(uint4*)((char*)Ahi + to0) = P[sl][0];
        *(uint4*)((char*)Alo + to0) = P[sl][1];
        *(uint4*)((char*)Bhi + to0) = P[sl][2];
        *(uint4*)((char*)Blo + to0) = P[sl][3];
        *(uint4*)((char*)Ahi + to1) = P[sl][4];
        *(uint4*)((char*)Alo + to1) = P[sl][5];
        *(uint4*)((char*)Bhi + to1) = P[sl][6];
        *(uint4*)((char*)Blo + to1) = P[sl][7];
        __syncthreads();

        if (ch + 2 < NCH) {
            const int c0 = (ch + 2) * BK;
            P[sl][0] = *((const uint4*)(shi + a0b + c0) + j0);
            P[sl][1] = *((const uint4*)(slo + a0b + c0) + j0);
            P[sl][2] = *((const uint4*)(whi + b0b + c0) + j0);
            P[sl][3] = *((const uint4*)(wlo + b0b + c0) + j0);
            P[sl][4] = *((const uint4*)(shi + a1b + c0) + j0);
            P[sl][5] = *((const uint4*)(slo + a1b + c0) + j0);
            P[sl][6] = *((const uint4*)(whi + b1b + c0) + j0);
            P[sl][7] = *((const uint4*)(wlo + b1b + c0) + j0);
        }

        #pragma unroll
        for (int ks = 0; ks < BK / 16; ++ks) {
            const int akb = ks * 32 + a_koff;
            const int bkb = ks * 32 + b_koff;
            unsigned ah[2][4], al[2][4];
            #pragma unroll
            for (int mt = 0; mt < 2; ++mt) {
                unsigned aoff = (unsigned)((wm + mt * 16 + a_row) * LDB + akb);
                ldsm4(ah[mt], uAhi + aoff);
                ldsm4(al[mt], uAlo + aoff);
            }
            #pragma unroll
            for (int n2 = 0; n2 < 4; ++n2) {
                unsigned boff = (unsigned)((wn + n2 * 16 + b_row) * LDB + bkb);
                unsigned bh[4], bl[4];
                ldsm4(bh, uBhi + boff);
                ldsm4(bl, uBlo + boff);
                #pragma unroll
                for (int mt = 0; mt < 2; ++mt) {
                    mma16816(acc[mt][n2 * 2],     ah[mt], bh);
                    mma16816(acc[mt][n2 * 2],     ah[mt], bl);
                    mma16816(acc[mt][n2 * 2],     al[mt], bh);
                    mma16816(acc[mt][n2 * 2 + 1], ah[mt], bh + 2);
                    mma16816(acc[mt][n2 * 2 + 1], ah[mt], bl + 2);
                    mma16816(acc[mt][n2 * 2 + 1], al[mt], bh + 2);
                }
            }
        }
        __syncthreads();
    }

    // ---- epilogue: smem transpose -> coalesced red.v4 scatter ----
    const int myp = (warp & 3) >> 1;
    const int cq = tid * 2;
    #pragma unroll
    for (int p = 0; p < 2; ++p) {
        if (myp == p) {
            #pragma unroll
            for (int mt = 0; mt < 2; ++mt)
                #pragma unroll
                for (int half = 0; half < 2; ++half) {
                    int lrow = (wm & 63) + mt * 16 + g + half * 8;
                    #pragma unroll
                    for (int na = 0; na < 8; ++na) {
                        int col = wn + na * 8 + cq;
                        *(float2*)&T[lrow * 132 + col] =
                            make_float2(acc[mt][na][half * 2],
                                        acc[mt][na][half * 2 + 1]);
                    }
                }
        }
        __syncthreads();
        #pragma unroll
        for (int i = 0; i < 8; ++i) {
            int lrow = i * 8 + warp;
            int cpos = lane * 4;
            int orow = sOut[p * 64 + lrow];
            if (orow >= 0) {
                float4 v = *(const float4*)&T[lrow * 132 + cpos];
                red_v4(dstbase + (size_t)orow * kCO + cpos, v);
            }
        }
        __syncthreads();
    }
}

// ---------------- skip GEMM (fp32 SIMT, TM=16 -> 128 blocks) ----------------
__global__ void __launch_bounds__(256)
skip_kernel(const float* __restrict__ feats,
            const float* __restrict__ w,
            const float* __restrict__ bias)
{
    constexpr int TM = 16, TK = 32, CIN = kC;
    __shared__ float Ws[TK * 128];
    __shared__ float Gs[TK][TM + 1];
    const int m0 = blockIdx.x * TM;
    const int t = threadIdx.x;

    float acc[8];
    #pragma unroll
    for (int j = 0; j < 8; ++j) acc[j] = 0.f;

    const int tr = t >> 4;
    const int tc = (t & 15) << 3;

    #pragma unroll 1
    for (int c0 = 0; c0 < CIN; c0 += TK) {
        {
            const float4* wsrc = (const float4*)(w + c0 * 128);
            float4* wdst = (float4*)Ws;
            #pragma unroll
            for (int i = 0; i < 4; ++i)
                wdst[t + i * 256] = wsrc[t + i * 256];
        }
        {
            const int c = t & 31;
            #pragma unroll
            for (int i = 0; i < 2; ++i) {
                int r = (t >> 5) + i * 8;
                Gs[c][r] = feats[(size_t)(m0 + r) * CIN + c0 + c];
            }
        }
        __syncthreads();
        #pragma unroll
        for (int kk = 0; kk < TK; ++kk) {
            float a0 = Gs[kk][tr];
            float4 b0 = *(const float4*)&Ws[kk * 128 + tc];
            float4 b1 = *(const float4*)&Ws[kk * 128 + tc + 4];
            float bv[8] = {b0.x, b0.y, b0.z, b0.w, b1.x, b1.y, b1.z, b1.w};
            #pragma unroll
            for (int j = 0; j < 8; ++j)
                acc[j] = fmaf(a0, bv[j], acc[j]);
        }
        __syncthreads();
    }
    int m = m0 + tr;
    #pragma unroll
    for (int j = 0; j < 8; ++j)
        g_skip[(size_t)m * kCO + tc + j] = acc[j] + bias[tc + j];
}

// ---------------- h1 epilogue: +bias -> LN -> SiLU -> bf16 hi/lo -------------
__global__ void h1_ep_kernel(const float* __restrict__ c1b) {
    const int m = blockIdx.x, t = threadIdx.x;   // 128
    const int wid = t >> 5, lane = t & 31;
    __shared__ float red[4];
    float x = g_h1acc[m * kCO + t] + c1b[t];
    float s = x;
    #pragma unroll
    for (int o = 16; o; o >>= 1) s += __shfl_xor_sync(0xffffffffu, s, o);
    if (lane == 0) red[wid] = s;
    __syncthreads();
    const float mean = (red[0] + red[1] + red[2] + red[3]) * (1.f / kCO);
    const float d = x - mean;
    float s2 = d * d;
    #pragma unroll
    for (int o = 16; o; o >>= 1) s2 += __shfl_xor_sync(0xffffffffu, s2, o);
    __syncthreads();
    if (lane == 0) red[wid] = s2;
    __syncthreads();
    const float var = (red[0] + red[1] + red[2] + red[3]) * (1.f / kCO);
    const float y = d * rsqrtf(var + 1e-6f);
    const float h = y / (1.f + expf(-y));
    __nv_bfloat16 hh = __float2bfloat16(h);
    g_h1hi[m * kCO + t] = hh;
    g_h1lo[m * kCO + t] = __float2bfloat16(h - __bfloat162float(hh));
}

// ---------------- out epilogue: += bias + skip (active rows) -----------------
__global__ void out_ep_kernel(float* __restrict__ out,
                              const float* __restrict__ c2b) {
    if ((int)blockIdx.x >= g_cnt) return;
    const int m = g_list[blockIdx.x], t = threadIdx.x;   // 128
    out[(size_t)m * kCO + t] += c2b[t] + g_skip[(size_t)(m >> 3) * kCO + t];
}

// ---------------- launch (ONLY harness pointers cross the boundary) ----------
extern "C" void kernel_launch(void* const* d_in, const int* in_sizes, int n_in,
                              void* d_out, int out_size)
{
    const float* feats = (const float*)d_in[0];
    const float* n1w   = (const float*)d_in[1];
    const float* n1b   = (const float*)d_in[2];
    const float* sdw   = (const float*)d_in[3];
    const float* sdb   = (const float*)d_in[4];
    const float* c1w   = (const float*)d_in[5];
    const float* c1b   = (const float*)d_in[6];
    const float* c2w   = (const float*)d_in[7];
    const float* c2b   = (const float*)d_in[8];
    const float* skw   = (const float*)d_in[9];
    const float* skb   = (const float*)d_in[10];
    const int*   coords= (const int*)d_in[11];

    float* out        = (float*)d_out;
    float* subdiv_out = out + (size_t)kM * kCO;

    prep_kernel<<<PREP_BLOCKS, 256>>>(out, c1w, c2w);
    scatter_kernel<<<kM / 256, 256>>>(coords);        // MUST follow sentinel fill
    row_kernel<<<kN, 256>>>(feats, n1w, n1b, sdw, sdb, subdiv_out);
    skip_kernel<<<kN / 16, 256>>>(feats, skw, skb);
    nidx_kernel<<<dim3(kM / 256, 9), 256>>>(coords);
    tap_scan_kernel<<<1, 32>>>();
    tap_fill_kernel<<<54, 256>>>();
    tapgemm_mma<1><<<27 * 128, 256>>>(nullptr);
    h1_ep_kernel<<<kM, 128>>>(c1b);
    tapgemm_mma<2><<<27 * 128, 256>>>(out);
    out_ep_kernel<<<kM, 128>>>(out, c2b);
}